// round 10
// baseline (speedup 1.0000x reference)
#include <cuda_runtime.h>
#include <cuda_bf16.h>
#include <cstdint>

// Problem constants
#define BB 4
#define SS 1024
#define DD 1024
#define HH 16
#define HD 64
#define MROWS (BB*SS)          // 4096
#define QSCALE 0.03125f        // 1024^-0.5

// ---------------------------------------------------------------------------
// Scratch
// ---------------------------------------------------------------------------
__device__ __nv_bfloat16 g_xh[(size_t)MROWS * DD],   g_xl[(size_t)MROWS * DD];
__device__ __nv_bfloat16 g_wih[(size_t)DD * 3 * DD], g_wil[(size_t)DD * 3 * DD];
__device__ __nv_bfloat16 g_woh[(size_t)DD * DD],     g_wol[(size_t)DD * DD];
__device__ __nv_bfloat16 g_qh[(size_t)BB*HH*SS*HD],  g_ql[(size_t)BB*HH*SS*HD];
__device__ __nv_bfloat16 g_kh[(size_t)BB*HH*SS*HD],  g_kl[(size_t)BB*HH*SS*HD];
__device__ __nv_bfloat16 g_vh[(size_t)BB*HH*SS*HD],  g_vl[(size_t)BB*HH*SS*HD];
__device__ __nv_bfloat16 g_ph[(size_t)BB*HH*SS*SS],  g_pl[(size_t)BB*HH*SS*SS];
__device__ __nv_bfloat16 g_aoh[(size_t)MROWS * DD],  g_aol[(size_t)MROWS * DD];

// ---------------------------------------------------------------------------
// MMA / ldmatrix / cp.async helpers
// ---------------------------------------------------------------------------
__device__ __forceinline__ void mma16816(float* d, const uint32_t* a, const uint32_t* b) {
    asm volatile(
        "mma.sync.aligned.m16n8k16.row.col.f32.bf16.bf16.f32 "
        "{%0,%1,%2,%3}, {%4,%5,%6,%7}, {%8,%9}, {%0,%1,%2,%3};"
        : "+f"(d[0]), "+f"(d[1]), "+f"(d[2]), "+f"(d[3])
        : "r"(a[0]), "r"(a[1]), "r"(a[2]), "r"(a[3]), "r"(b[0]), "r"(b[1]));
}
__device__ __forceinline__ void ldsm_x4(uint32_t* r, uint32_t addr) {
    asm volatile("ldmatrix.sync.aligned.m8n8.x4.shared.b16 {%0,%1,%2,%3}, [%4];"
                 : "=r"(r[0]), "=r"(r[1]), "=r"(r[2]), "=r"(r[3]) : "r"(addr));
}
__device__ __forceinline__ void ldsm_x2t(uint32_t* r, uint32_t addr) {
    asm volatile("ldmatrix.sync.aligned.m8n8.x2.trans.shared.b16 {%0,%1}, [%2];"
                 : "=r"(r[0]), "=r"(r[1]) : "r"(addr));
}
__device__ __forceinline__ void split_bf16(float v, __nv_bfloat16& h, __nv_bfloat16& l) {
    h = __float2bfloat16(v);
    l = __float2bfloat16(v - __bfloat162float(h));
}
__device__ __forceinline__ void cpa16(uint32_t s, const void* g) {
    asm volatile("cp.async.cg.shared.global [%0], [%1], 16;" :: "r"(s), "l"(g));
}
__device__ __forceinline__ void cp_commit() { asm volatile("cp.async.commit_group;"); }
template<int N> __device__ __forceinline__ void cp_wait() {
    asm volatile("cp.async.wait_group %0;" :: "n"(N));
}

// ---------------------------------------------------------------------------
// split kernel: fp32 -> (hi, lo) bf16
// ---------------------------------------------------------------------------
__global__ __launch_bounds__(256) void split_kernel(
    const float* __restrict__ in, __nv_bfloat16* __restrict__ hi,
    __nv_bfloat16* __restrict__ lo, int n4)
{
    int i = blockIdx.x * 256 + threadIdx.x;
    if (i >= n4) return;
    float4 v = ((const float4*)in)[i];
    __nv_bfloat16 h0, l0, h1, l1, h2, l2, h3, l3;
    split_bf16(v.x, h0, l0); split_bf16(v.y, h1, l1);
    split_bf16(v.z, h2, l2); split_bf16(v.w, h3, l3);
    ((__nv_bfloat162*)hi)[2 * i]     = __nv_bfloat162(h0, h1);
    ((__nv_bfloat162*)hi)[2 * i + 1] = __nv_bfloat162(h2, h3);
    ((__nv_bfloat162*)lo)[2 * i]     = __nv_bfloat162(l0, l1);
    ((__nv_bfloat162*)lo)[2 * i + 1] = __nv_bfloat162(l2, l3);
}

// ---------------------------------------------------------------------------
// GEMM tile (BM=BN=128, BK=32): 4 warps (128 thr), warp tile 64x64.
// 3-stage cp.async pipeline, one barrier per iter.
// ---------------------------------------------------------------------------
#define ASTR 40
#define BSTR 136
#define AH_OFF 0
#define AL_OFF 10240
#define BH_OFF 20480
#define BL_OFF 29184
#define STAGE_B 37888
#define GEMM_SMEM (STAGE_B * 3)

#define GEMM_PROLOG(p3expr) \
    extern __shared__ char dynsm[]; \
    uint32_t smbase = (uint32_t)__cvta_generic_to_shared(dynsm); \
    int bx = blockIdx.x, by = blockIdx.y; \
    int tid = threadIdx.x, lane = tid & 31, wid = tid >> 5; \
    int wm = (wid & 1) * 64, wn = (wid >> 1) * 64; \
    const bool p3 = (p3expr); \
    uint32_t a_off = (uint32_t)((wm + (lane & 15)) * ASTR + (lane >> 4) * 8) * 2; \
    uint32_t b_off = (uint32_t)((lane & 15) * BSTR + wn) * 2; \
    float acc[4][8][4]; \
    _Pragma("unroll") for (int i = 0; i < 4; i++) \
        _Pragma("unroll") for (int j = 0; j < 8; j++) \
            _Pragma("unroll") for (int c = 0; c < 4; c++) acc[i][j][c] = 0.f; \
    const int nk = K >> 5; \
    auto load_stage = [&](int st, int kt) { \
        uint32_t sb = smbase + st * STAGE_B; \
        _Pragma("unroll") for (int i = 0; i < 4; i++) { \
            int row = (tid >> 2) + i * 32; \
            size_t g = (size_t)(by * 128 + row) * K + kt + (tid & 3) * 8; \
            cpa16(sb + AH_OFF + (uint32_t)(row * ASTR + (tid & 3) * 8) * 2, Ahg + g); \
            cpa16(sb + AL_OFF + (uint32_t)(row * ASTR + (tid & 3) * 8) * 2, Alg + g); \
        } \
        _Pragma("unroll") for (int i = 0; i < 4; i++) { \
            int row = (tid >> 4) + i * 8; \
            size_t g = (size_t)(kt + row) * N + bx * 128 + (tid & 15) * 8; \
            cpa16(sb + BH_OFF + (uint32_t)(row * BSTR + (tid & 15) * 8) * 2, Bhg + g); \
            if (p3) cpa16(sb + BL_OFF + (uint32_t)(row * BSTR + (tid & 15) * 8) * 2, Blg + g); \
        } \
        cp_commit(); \
    }; \
    load_stage(0, 0); \
    load_stage(1, 32); \
    for (int i = 0; i < nk; i++) { \
        if (i + 1 < nk) cp_wait<1>(); else cp_wait<0>(); \
        __syncthreads(); \
        if (i + 2 < nk) load_stage((i + 2) % 3, (i + 2) * 32); \
        uint32_t sb = smbase + (i % 3) * STAGE_B; \
        _Pragma("unroll") for (int ks = 0; ks < 2; ks++) { \
            uint32_t ahf[4][4], alf[4][4]; \
            _Pragma("unroll") for (int mi = 0; mi < 4; mi++) { \
                uint32_t off = a_off + (uint32_t)(mi * 16 * ASTR + ks * 16) * 2; \
                ldsm_x4(ahf[mi], sb + AH_OFF + off); \
                ldsm_x4(alf[mi], sb + AL_OFF + off); \
            } \
            _Pragma("unroll") for (int nb = 0; nb < 2; nb++) { \
                uint32_t bhf[4][2]; \
                _Pragma("unroll") for (int nj = 0; nj < 4; nj++) { \
                    uint32_t off = b_off + (uint32_t)(ks * 16 * BSTR + (nb * 4 + nj) * 8) * 2; \
                    ldsm_x2t(bhf[nj], sb + BH_OFF + off); \
                } \
                _Pragma("unroll") for (int nj = 0; nj < 4; nj++) \
                    _Pragma("unroll") for (int mi = 0; mi < 4; mi++) \
                        mma16816(acc[mi][nb * 4 + nj], ahf[mi], bhf[nj]); \
                _Pragma("unroll") for (int nj = 0; nj < 4; nj++) \
                    _Pragma("unroll") for (int mi = 0; mi < 4; mi++) \
                        mma16816(acc[mi][nb * 4 + nj], alf[mi], bhf[nj]); \
                if (p3) { \
                    uint32_t blf[4][2]; \
                    _Pragma("unroll") for (int nj = 0; nj < 4; nj++) { \
                        uint32_t off = b_off + (uint32_t)(ks * 16 * BSTR + (nb * 4 + nj) * 8) * 2; \
                        ldsm_x2t(blf[nj], sb + BL_OFF + off); \
                    } \
                    _Pragma("unroll") for (int nj = 0; nj < 4; nj++) \
                        _Pragma("unroll") for (int mi = 0; mi < 4; mi++) \
                            mma16816(acc[mi][nb * 4 + nj], ahf[mi], blf[nj]); \
                } \
            } \
        } \
    } \
    __syncthreads();

// ---------------------------------------------------------------------------
// QKV GEMM: writes q (scaled), k, v as split bf16 in [b,h,s,d] layout
// ---------------------------------------------------------------------------
__global__ __launch_bounds__(128, 2) void mma_gemm_qkv(
    const __nv_bfloat16* __restrict__ Ahg, const __nv_bfloat16* __restrict__ Alg,
    const __nv_bfloat16* __restrict__ Bhg, const __nv_bfloat16* __restrict__ Blg,
    const float* __restrict__ bias,
    __nv_bfloat16* __restrict__ qh, __nv_bfloat16* __restrict__ ql,
    __nv_bfloat16* __restrict__ kh, __nv_bfloat16* __restrict__ kl,
    __nv_bfloat16* __restrict__ vh, __nv_bfloat16* __restrict__ vl,
    int M, int N, int K)
{
    GEMM_PROLOG(blockIdx.x >= 16)   // v part gets 3 passes

    int part = (bx * 128) >> 10;
    __nv_bfloat16* dh = part == 0 ? qh : (part == 1 ? kh : vh);
    __nv_bfloat16* dl = part == 0 ? ql : (part == 1 ? kl : vl);
    float mul = part == 0 ? QSCALE : 1.0f;
    int head = ((bx * 128 + wn) & 1023) >> 6;
    int bq = (by * 128) >> 10;
    int group = lane >> 2, tig = lane & 3;
    #pragma unroll
    for (int mi = 0; mi < 4; mi++) {
        int s0 = ((by * 128) & 1023) + wm + mi * 16 + group;
        #pragma unroll
        for (int ni = 0; ni < 8; ni++) {
            int col = bx * 128 + wn + ni * 8 + tig * 2;
            int d = ni * 8 + tig * 2;
            float b0 = bias[col], b1 = bias[col + 1];
            float v00 = (acc[mi][ni][0] + b0) * mul, v01 = (acc[mi][ni][1] + b1) * mul;
            float v10 = (acc[mi][ni][2] + b0) * mul, v11 = (acc[mi][ni][3] + b1) * mul;
            size_t o0 = ((size_t)(bq * HH + head) * SS + s0) * HD + d;
            size_t o1 = o0 + 8 * HD;
            __nv_bfloat16 h0, l0, h1, l1;
            split_bf16(v00, h0, l0); split_bf16(v01, h1, l1);
            *(__nv_bfloat162*)&dh[o0] = __nv_bfloat162(h0, h1);
            *(__nv_bfloat162*)&dl[o0] = __nv_bfloat162(l0, l1);
            split_bf16(v10, h0, l0); split_bf16(v11, h1, l1);
            *(__nv_bfloat162*)&dh[o1] = __nv_bfloat162(h0, h1);
            *(__nv_bfloat162*)&dl[o1] = __nv_bfloat162(l0, l1);
        }
    }
}

// ---------------------------------------------------------------------------
// Out-projection GEMM: fp32 output + bias, full 3-pass
// ---------------------------------------------------------------------------
__global__ __launch_bounds__(128, 2) void mma_gemm_out(
    const __nv_bfloat16* __restrict__ Ahg, const __nv_bfloat16* __restrict__ Alg,
    const __nv_bfloat16* __restrict__ Bhg, const __nv_bfloat16* __restrict__ Blg,
    const float* __restrict__ bias, float* __restrict__ C,
    int M, int N, int K)
{
    GEMM_PROLOG(true)

    int group = lane >> 2, tig = lane & 3;
    #pragma unroll
    for (int mi = 0; mi < 4; mi++) {
        int row0 = by * 128 + wm + mi * 16 + group;
        #pragma unroll
        for (int ni = 0; ni < 8; ni++) {
            int col = bx * 128 + wn + ni * 8 + tig * 2;
            float b0 = bias[col], b1 = bias[col + 1];
            *(float2*)&C[(size_t)row0 * N + col] =
                make_float2(acc[mi][ni][0] + b0, acc[mi][ni][1] + b1);
            *(float2*)&C[(size_t)(row0 + 8) * N + col] =
                make_float2(acc[mi][ni][2] + b0, acc[mi][ni][3] + b1);
        }
    }
}

// ---------------------------------------------------------------------------
// Scores + softmax (MMA): per (b,h,32q). 2-pass: S = qh*kh + ql*kh.
// K-chunks of 256; 8 warps = 2m x 4n, warp tile 16q x 64k-cols.
// smem: Ssc fp32[32][1032] | Qh/Ql [32][72] | Kh x2 stages [256][72]
// ---------------------------------------------------------------------------
#define SC2_QH 132096
#define SC2_QL 136704
#define SC2_K  141312
#define SC2_KSTAGE 36864
#define SC2_SMEM 215040

__global__ __launch_bounds__(256) void attn_scores_mma(
    const __nv_bfloat16* __restrict__ qh, const __nv_bfloat16* __restrict__ ql,
    const __nv_bfloat16* __restrict__ kh,
    __nv_bfloat16* __restrict__ Ph, __nv_bfloat16* __restrict__ Pl)
{
    extern __shared__ char dynsm[];
    float* Ssc = (float*)dynsm;
    uint32_t smbase = (uint32_t)__cvta_generic_to_shared(dynsm);

    int b = blockIdx.z, h = blockIdx.y, q0 = blockIdx.x * 32;
    int tid = threadIdx.x, lane = tid & 31, wid = tid >> 5;
    int wm = (wid & 1) * 16;         // 2 m-groups over 32 q
    int wn = (wid >> 1) * 64;        // 4 n-groups of 64 over 256-k chunk

    {
        size_t qb = ((size_t)(b * HH + h) * SS + q0) * HD;
        int row = tid >> 3, c8 = (tid & 7) * 8;
        *(uint4*)(dynsm + SC2_QH + (row * 72 + c8) * 2) = *(const uint4*)&qh[qb + row * 64 + c8];
        *(uint4*)(dynsm + SC2_QL + (row * 72 + c8) * 2) = *(const uint4*)&ql[qb + row * 64 + c8];
    }

    auto load_k = [&](int st, int kt) {
        uint32_t kb = smbase + SC2_K + st * SC2_KSTAGE;
        size_t gb = ((size_t)(b * HH + h) * SS + kt) * HD;
        #pragma unroll
        for (int it = 0; it < 8; it++) {
            int idx = tid + it * 256;
            int row = idx >> 3, c8 = (idx & 7) * 8;
            cpa16(kb + (uint32_t)(row * 72 + c8) * 2, kh + gb + (size_t)row * 64 + c8);
        }
        cp_commit();
    };
    load_k(0, 0);
    load_k(1, 256);

    uint32_t aq_off = (uint32_t)((wm + (lane & 15)) * 72 + (lane >> 4) * 8) * 2;
    int rr_ = lane & 7, halfk = (lane >> 3) & 1, q2 = lane >> 4;

    for (int i = 0; i < 4; i++) {
        if (i < 3) cp_wait<1>(); else cp_wait<0>();
        __syncthreads();
        uint32_t kb = smbase + SC2_K + (i & 1) * SC2_KSTAGE;

        float acc[8][4];
        #pragma unroll
        for (int a = 0; a < 8; a++)
            #pragma unroll
            for (int c = 0; c < 4; c++) acc[a][c] = 0.f;

        #pragma unroll
        for (int ks = 0; ks < 4; ks++) {
            uint32_t ahf[4], alf[4];
            ldsm_x4(ahf, smbase + SC2_QH + aq_off + ks * 32);
            ldsm_x4(alf, smbase + SC2_QL + aq_off + ks * 32);
            uint32_t bhf[4][4];
            #pragma unroll
            for (int nb = 0; nb < 4; nb++) {
                uint32_t boff = (uint32_t)((wn + nb * 16 + q2 * 8 + rr_) * 72 + halfk * 8 + ks * 16) * 2;
                ldsm_x4(bhf[nb], kb + boff);
            }
            // pass 1: qh*kh
            #pragma unroll
            for (int nb = 0; nb < 4; nb++) {
                mma16816(acc[nb*2],   ahf, bhf[nb]);
                mma16816(acc[nb*2+1], ahf, bhf[nb] + 2);
            }
            // pass 2: ql*kh
            #pragma unroll
            for (int nb = 0; nb < 4; nb++) {
                mma16816(acc[nb*2],   alf, bhf[nb]);
                mma16816(acc[nb*2+1], alf, bhf[nb] + 2);
            }
        }

        int kt = i * 256;
        int group = lane >> 2, tig = lane & 3;
        #pragma unroll
        for (int ni = 0; ni < 8; ni++) {
            int row = wm + group;
            int col = kt + wn + ni * 8 + tig * 2;
            *(float2*)&Ssc[row * 1032 + col]       = make_float2(acc[ni][0], acc[ni][1]);
            *(float2*)&Ssc[(row + 8) * 1032 + col] = make_float2(acc[ni][2], acc[ni][3]);
        }
        __syncthreads();
        if (i + 2 < 4) load_k((i + 2) & 1, (i + 2) * 256);
    }

    for (int rr = 0; rr < 4; rr++) {
        int row = wid * 4 + rr;
        float2 v2[16];
        float m = -1e30f;
        #pragma unroll
        for (int i2 = 0; i2 < 16; i2++) {
            v2[i2] = *(float2*)&Ssc[row * 1032 + (lane + i2 * 32) * 2];
            m = fmaxf(m, fmaxf(v2[i2].x, v2[i2].y));
        }
        #pragma unroll
        for (int o = 16; o; o >>= 1) m = fmaxf(m, __shfl_xor_sync(0xffffffffu, m, o));
        float s = 0.f;
        #pragma unroll
        for (int i2 = 0; i2 < 16; i2++) {
            v2[i2].x = __expf(v2[i2].x - m);
            v2[i2].y = __expf(v2[i2].y - m);
            s += v2[i2].x + v2[i2].y;
        }
        #pragma unroll
        for (int o = 16; o; o >>= 1) s += __shfl_xor_sync(0xffffffffu, s, o);
        float inv = 1.f / s;
        size_t gb = ((size_t)(b * HH + h) * SS + q0 + row) * SS;
        #pragma unroll
        for (int i2 = 0; i2 < 16; i2++) {
            float p0 = v2[i2].x * inv, p1 = v2[i2].y * inv;
            __nv_bfloat16 h0, l0, h1, l1;
            split_bf16(p0, h0, l0); split_bf16(p1, h1, l1);
            size_t o = gb + (size_t)(lane + i2 * 32) * 2;
            *(__nv_bfloat162*)&Ph[o] = __nv_bfloat162(h0, h1);
            *(__nv_bfloat162*)&Pl[o] = __nv_bfloat162(l0, l1);
        }
    }
}

// ---------------------------------------------------------------------------
// PV (MMA): AO = P @ V per (b,h,256q). 8 warps x (32q x 64d) warp tiles.
// Full 3-pass. 2-stage cp.async.
// ---------------------------------------------------------------------------
#define PV_PH 0
#define PV_PL 36864
#define PV_VH 73728
#define PV_VL 82944
#define PV_STAGE 92160
#define PV_SMEM 184320

__global__ __launch_bounds__(256) void attn_pv_mma(
    const __nv_bfloat16* __restrict__ Ph, const __nv_bfloat16* __restrict__ Pl,
    const __nv_bfloat16* __restrict__ vh, const __nv_bfloat16* __restrict__ vl,
    __nv_bfloat16* __restrict__ AOh, __nv_bfloat16* __restrict__ AOl)
{
    extern __shared__ char dynsm[];
    uint32_t smbase = (uint32_t)__cvta_generic_to_shared(dynsm);

    int b = blockIdx.z, h = blockIdx.y, q0 = blockIdx.x * 256;
    int tid = threadIdx.x, lane = tid & 31, wid = tid >> 5;

    auto load_stage = [&](int st, int kt) {
        uint32_t sb = smbase + st * PV_STAGE;
        size_t pb = ((size_t)(b * HH + h) * SS + q0) * SS + kt;
        #pragma unroll
        for (int it = 0; it < 8; it++) {
            int idx = tid + it * 256;
            int row = idx >> 3, c8 = (idx & 7) * 8;
            cpa16(sb + PV_PH + (uint32_t)(row * 72 + c8) * 2, Ph + pb + (size_t)row * SS + c8);
            cpa16(sb + PV_PL + (uint32_t)(row * 72 + c8) * 2, Pl + pb + (size_t)row * SS + c8);
        }
        size_t vb = ((size_t)(b * HH + h) * SS + kt) * HD;
        #pragma unroll
        for (int it = 0; it < 2; it++) {
            int idx = tid + it * 256;
            int row = idx >> 3, c8 = (idx & 7) * 8;
            cpa16(sb + PV_VH + (uint32_t)(row * 72 + c8) * 2, vh + vb + row * 64 + c8);
            cpa16(sb + PV_VL + (uint32_t)(row * 72 + c8) * 2, vl + vb + row * 64 + c8);
        }
        cp_commit();
    };

    float acc[2][8][4];
    #pragma unroll
    for (int a = 0; a < 2; a++)
        #pragma unroll
        for (int j = 0; j < 8; j++)
            #pragma unroll
            for (int c = 0; c < 4; c++) acc[a][j][c] = 0.f;

    uint32_t ap_off = (uint32_t)((wid * 32 + (lane & 15)) * 72 + (lane >> 4) * 8) * 2;
    uint32_t bv_off = (uint32_t)((lane & 15) * 72) * 2;

    load_stage(0, 0);
    load_stage(1, 64);

    for (int i = 0; i < 16; i++) {
        if (i < 15) cp_wait<1>(); else cp_wait<0>();
        __syncthreads();
        uint32_t sb = smbase + (i & 1) * PV_STAGE;
        #pragma unroll
        for (int ks = 0; ks < 4; ks++) {
            uint32_t ahf[2][4], alf[2][4];
            #pragma unroll
            for (int mi = 0; mi < 2; mi++) {
                uint32_t off = ap_off + (uint32_t)(mi * 16 * 72 + ks * 16) * 2;
                ldsm_x4(ahf[mi], sb + PV_PH + off);
                ldsm_x4(alf[mi], sb + PV_PL + off);
            }
            #pragma unroll
            for (int nb = 0; nb < 2; nb++) {
                uint32_t bhf[4][2], blf[4][2];
                #pragma unroll
                for (int nj = 0; nj < 4; nj++) {
                    uint32_t off = bv_off + (uint32_t)(ks * 16 * 72 + (nb * 4 + nj) * 8) * 2;
                    ldsm_x2t(bhf[nj], sb + PV_VH + off);
                    ldsm_x2t(blf[nj], sb + PV_VL + off);
                }
                #pragma unroll
                for (int nj = 0; nj < 4; nj++)
                    #pragma unroll
                    for (int mi = 0; mi < 2; mi++)
                        mma16816(acc[mi][nb*4+nj], ahf[mi], bhf[nj]);
                #pragma unroll
                for (int nj = 0; nj < 4; nj++)
                    #pragma unroll
                    for (int mi = 0; mi < 2; mi++)
                        mma16816(acc[mi][nb*4+nj], ahf[mi], blf[nj]);
                #pragma unroll
                for (int nj = 0; nj < 4; nj++)
                    #pragma unroll
                    for (int mi = 0; mi < 2; mi++)
                        mma16816(acc[mi][nb*4+nj], alf[mi], bhf[nj]);
            }
        }
        __syncthreads();
        if (i + 2 < 16) load_stage((i + 2) & 1, (i + 2) * 64);
    }

    int group = lane >> 2, tig = lane & 3;
    #pragma unroll
    for (int mi = 0; mi < 2; mi++) {
        #pragma unroll
        for (int ni = 0; ni < 8; ni++) {
            int d = ni * 8 + tig * 2;
            int r0 = q0 + wid * 32 + mi * 16 + group;
            size_t o0 = (size_t)(b * SS + r0) * DD + h * HD + d;
            size_t o1 = o0 + (size_t)8 * DD;
            __nv_bfloat16 h0, l0, h1, l1;
            split_bf16(acc[mi][ni][0], h0, l0); split_bf16(acc[mi][ni][1], h1, l1);
            *(__nv_bfloat162*)&AOh[o0] = __nv_bfloat162(h0, h1);
            *(__nv_bfloat162*)&AOl[o0] = __nv_bfloat162(l0, l1);
            split_bf16(acc[mi][ni][2], h0, l0); split_bf16(acc[mi][ni][3], h1, l1);
            *(__nv_bfloat162*)&AOh[o1] = __nv_bfloat162(h0, h1);
            *(__nv_bfloat162*)&AOl[o1] = __nv_bfloat162(l0, l1);
        }
    }
}

// ---------------------------------------------------------------------------
// attn_mean[b,q,k] = (1/H) * sum_h (Ph + Pl)
// ---------------------------------------------------------------------------
__global__ __launch_bounds__(256) void attn_mean_kernel(
    const __nv_bfloat16* __restrict__ Ph, const __nv_bfloat16* __restrict__ Pl,
    float* __restrict__ outm)
{
    size_t g = (size_t)blockIdx.x * 256 + threadIdx.x;
    int k8 = (int)(g & 127);
    size_t t = g >> 7;
    int q = (int)(t & 1023);
    int b = (int)(t >> 10);
    size_t k = (size_t)k8 * 8;

    float acc8[8];
    #pragma unroll
    for (int j = 0; j < 8; j++) acc8[j] = 0.f;
    #pragma unroll
    for (int h = 0; h < HH; h++) {
        size_t off = ((size_t)(b * HH + h) * SS + q) * SS + k;
        uint4 vh4 = *(const uint4*)&Ph[off];
        uint4 vl4 = *(const uint4*)&Pl[off];
        const uint32_t* ph = (const uint32_t*)&vh4;
        const uint32_t* pl = (const uint32_t*)&vl4;
        #pragma unroll
        for (int j = 0; j < 4; j++) {
            __nv_bfloat162 hh = *(__nv_bfloat162*)&ph[j];
            __nv_bfloat162 ll = *(__nv_bfloat162*)&pl[j];
            acc8[2*j]   += __low2float(hh)  + __low2float(ll);
            acc8[2*j+1] += __high2float(hh) + __high2float(ll);
        }
    }
    size_t ob = ((size_t)(b * SS + q)) * SS + k;
    const float inv = 1.0f / HH;
    float4 o0 = make_float4(acc8[0]*inv, acc8[1]*inv, acc8[2]*inv, acc8[3]*inv);
    float4 o1 = make_float4(acc8[4]*inv, acc8[5]*inv, acc8[6]*inv, acc8[7]*inv);
    *(float4*)&outm[ob]     = o0;
    *(float4*)&outm[ob + 4] = o1;
}

// ---------------------------------------------------------------------------
// Host launcher (fork-join: attn_mean overlaps PV + out-proj on a side stream)
// ---------------------------------------------------------------------------
extern "C" void kernel_launch(void* const* d_in, const int* in_sizes, int n_in,
                              void* d_out, int out_size)
{
    const float* x     = (const float*)d_in[0];
    const float* w_in  = (const float*)d_in[1];
    const float* b_in  = (const float*)d_in[2];
    const float* w_out = (const float*)d_in[3];
    const float* b_out = (const float*)d_in[4];
    float* out = (float*)d_out;

    __nv_bfloat16 *xh, *xl, *wih, *wil, *woh, *wol;
    __nv_bfloat16 *qh, *ql, *kh, *kl, *vh, *vl, *ph, *pl, *aoh, *aol;
    cudaGetSymbolAddress((void**)&xh,  g_xh);
    cudaGetSymbolAddress((void**)&xl,  g_xl);
    cudaGetSymbolAddress((void**)&wih, g_wih);
    cudaGetSymbolAddress((void**)&wil, g_wil);
    cudaGetSymbolAddress((void**)&woh, g_woh);
    cudaGetSymbolAddress((void**)&wol, g_wol);
    cudaGetSymbolAddress((void**)&qh,  g_qh);
    cudaGetSymbolAddress((void**)&ql,  g_ql);
    cudaGetSymbolAddress((void**)&kh,  g_kh);
    cudaGetSymbolAddress((void**)&kl,  g_kl);
    cudaGetSymbolAddress((void**)&vh,  g_vh);
    cudaGetSymbolAddress((void**)&vl,  g_vl);
    cudaGetSymbolAddress((void**)&ph,  g_ph);
    cudaGetSymbolAddress((void**)&pl,  g_pl);
    cudaGetSymbolAddress((void**)&aoh, g_aoh);
    cudaGetSymbolAddress((void**)&aol, g_aol);

    static cudaStream_t s1 = nullptr;
    static cudaEvent_t evA = nullptr, evB = nullptr;
    if (!s1) {
        cudaStreamCreateWithFlags(&s1, cudaStreamNonBlocking);
        cudaEventCreateWithFlags(&evA, cudaEventDisableTiming);
        cudaEventCreateWithFlags(&evB, cudaEventDisableTiming);
    }

    cudaFuncSetAttribute(mma_gemm_qkv,
                         cudaFuncAttributeMaxDynamicSharedMemorySize, GEMM_SMEM);
    cudaFuncSetAttribute(mma_gemm_out,
                         cudaFuncAttributeMaxDynamicSharedMemorySize, GEMM_SMEM);
    cudaFuncSetAttribute(attn_scores_mma,
                         cudaFuncAttributeMaxDynamicSharedMemorySize, SC2_SMEM);
    cudaFuncSetAttribute(attn_pv_mma,
                         cudaFuncAttributeMaxDynamicSharedMemorySize, PV_SMEM);

    // 0. pre-split inputs
    split_kernel<<<(MROWS * DD / 4 + 255) / 256, 256>>>(x, xh, xl, MROWS * DD / 4);
    split_kernel<<<(DD * 3 * DD / 4 + 255) / 256, 256>>>(w_in, wih, wil, DD * 3 * DD / 4);
    split_kernel<<<(DD * DD / 4 + 255) / 256, 256>>>(w_out, woh, wol, DD * DD / 4);

    // 1. QKV GEMM -> split q/k/v per head (q,k 2-pass; v 3-pass)
    mma_gemm_qkv<<<dim3(3 * DD / 128, MROWS / 128), 128, GEMM_SMEM>>>(
        xh, xl, wih, wil, b_in, qh, ql, kh, kl, vh, vl, MROWS, 3 * DD, DD);

    // 2. scores + softmax (2-pass MMA) -> split P
    attn_scores_mma<<<dim3(SS / 32, HH, BB), 256, SC2_SMEM>>>(qh, ql, kh, ph, pl);

    // fork: head-mean (DRAM-bound) runs on side stream, overlapping PV+out-proj
    cudaEventRecord(evA, 0);
    cudaStreamWaitEvent(s1, evA, 0);
    attn_mean_kernel<<<(BB * SS * SS / 8) / 256, 256, 0, s1>>>(
        ph, pl, out + (size_t)BB * SS * SS);
    cudaEventRecord(evB, s1);

    // 3. P @ V (3-pass MMA, 256q CTAs) -> split AO
    attn_pv_mma<<<dim3(SS / 256, HH, BB), 256, PV_SMEM>>>(ph, pl, vh, vl, aoh, aol);

    // 5. output projection (3-pass)
    mma_gemm_out<<<dim3(DD / 128, MROWS / 128), 128, GEMM_SMEM>>>(
        aoh, aol, woh, wol, b_out, out, MROWS, DD, DD);

    // join
    cudaStreamWaitEvent(0, evB, 0);
}

// round 11
// speedup vs baseline: 1.1086x; 1.1086x over previous
#include <cuda_runtime.h>
#include <cuda_fp16.h>
#include <cstdint>

// Problem constants
#define BB 4
#define SS 1024
#define DD 1024
#define HH 16
#define HD 64
#define MROWS (BB*SS)          // 4096
#define QSCALE 0.03125f        // 1024^-0.5 (exact power of 2)
#define WSCALE 64.0f           // weight pre-scale (keeps fp16 lo out of subnormals)
#define AOSCALE 16.0f          // AO pre-scale

// ---------------------------------------------------------------------------
// Scratch (fp16 split format)
// ---------------------------------------------------------------------------
__device__ __half g_xh[(size_t)MROWS * DD],   g_xl[(size_t)MROWS * DD];
__device__ __half g_wih[(size_t)DD * 3 * DD], g_wil[(size_t)DD * 3 * DD];  // 64*w_in
__device__ __half g_woh[(size_t)DD * DD],     g_wol[(size_t)DD * DD];      // 64*w_out
__device__ __half g_q[(size_t)BB*HH*SS*HD];   // hi only (1-pass scores)
__device__ __half g_k[(size_t)BB*HH*SS*HD];   // hi only
__device__ __half g_v[(size_t)BB*HH*SS*HD];   // hi only (PV 2-pass)
__device__ __half g_ph[(size_t)BB*HH*SS*SS],  g_pl[(size_t)BB*HH*SS*SS];
__device__ __half g_aoh[(size_t)MROWS * DD],  g_aol[(size_t)MROWS * DD];   // 16*AO

// ---------------------------------------------------------------------------
// MMA / ldmatrix / cp.async helpers (fp16)
// ---------------------------------------------------------------------------
__device__ __forceinline__ void mma16816(float* d, const uint32_t* a, const uint32_t* b) {
    asm volatile(
        "mma.sync.aligned.m16n8k16.row.col.f32.f16.f16.f32 "
        "{%0,%1,%2,%3}, {%4,%5,%6,%7}, {%8,%9}, {%0,%1,%2,%3};"
        : "+f"(d[0]), "+f"(d[1]), "+f"(d[2]), "+f"(d[3])
        : "r"(a[0]), "r"(a[1]), "r"(a[2]), "r"(a[3]), "r"(b[0]), "r"(b[1]));
}
__device__ __forceinline__ void ldsm_x4(uint32_t* r, uint32_t addr) {
    asm volatile("ldmatrix.sync.aligned.m8n8.x4.shared.b16 {%0,%1,%2,%3}, [%4];"
                 : "=r"(r[0]), "=r"(r[1]), "=r"(r[2]), "=r"(r[3]) : "r"(addr));
}
__device__ __forceinline__ void ldsm_x2t(uint32_t* r, uint32_t addr) {
    asm volatile("ldmatrix.sync.aligned.m8n8.x2.trans.shared.b16 {%0,%1}, [%2];"
                 : "=r"(r[0]), "=r"(r[1]) : "r"(addr));
}
__device__ __forceinline__ void split_fp16(float v, __half& h, __half& l) {
    h = __float2half_rn(v);
    l = __float2half_rn(v - __half2float(h));
}
__device__ __forceinline__ void cpa16(uint32_t s, const void* g) {
    asm volatile("cp.async.cg.shared.global [%0], [%1], 16;" :: "r"(s), "l"(g));
}
__device__ __forceinline__ void cp_commit() { asm volatile("cp.async.commit_group;"); }
template<int N> __device__ __forceinline__ void cp_wait() {
    asm volatile("cp.async.wait_group %0;" :: "n"(N));
}

// ---------------------------------------------------------------------------
// split kernel: fp32 -> (hi, lo) fp16, with pre-scale
// ---------------------------------------------------------------------------
__global__ __launch_bounds__(256) void split_kernel(
    const float* __restrict__ in, __half* __restrict__ hi,
    __half* __restrict__ lo, float scale, int n4)
{
    int i = blockIdx.x * 256 + threadIdx.x;
    if (i >= n4) return;
    float4 v = ((const float4*)in)[i];
    __half h0, l0, h1, l1, h2, l2, h3, l3;
    split_fp16(v.x * scale, h0, l0); split_fp16(v.y * scale, h1, l1);
    split_fp16(v.z * scale, h2, l2); split_fp16(v.w * scale, h3, l3);
    ((__half2*)hi)[2 * i]     = __halves2half2(h0, h1);
    ((__half2*)hi)[2 * i + 1] = __halves2half2(h2, h3);
    ((__half2*)lo)[2 * i]     = __halves2half2(l0, l1);
    ((__half2*)lo)[2 * i + 1] = __halves2half2(l2, l3);
}

// ---------------------------------------------------------------------------
// GEMM tile (BM=BN=128, BK=32): 4 warps, warp tile 64x64.
// 3-stage cp.async pipeline. Pass structure per CTA:
//   useAl: add al*bh; useBl: add ah*bl. (1/2/3-pass configurations)
// ---------------------------------------------------------------------------
#define ASTR 40
#define BSTR 136
#define AH_OFF 0
#define AL_OFF 10240
#define BH_OFF 20480
#define BL_OFF 29184
#define STAGE_B 37888
#define GEMM_SMEM (STAGE_B * 3)

#define GEMM_PROLOG(useAlExpr, useBlExpr) \
    extern __shared__ char dynsm[]; \
    uint32_t smbase = (uint32_t)__cvta_generic_to_shared(dynsm); \
    int bx = blockIdx.x, by = blockIdx.y; \
    int tid = threadIdx.x, lane = tid & 31, wid = tid >> 5; \
    int wm = (wid & 1) * 64, wn = (wid >> 1) * 64; \
    const bool useAl = (useAlExpr), useBl = (useBlExpr); \
    uint32_t a_off = (uint32_t)((wm + (lane & 15)) * ASTR + (lane >> 4) * 8) * 2; \
    uint32_t b_off = (uint32_t)((lane & 15) * BSTR + wn) * 2; \
    float acc[4][8][4]; \
    _Pragma("unroll") for (int i = 0; i < 4; i++) \
        _Pragma("unroll") for (int j = 0; j < 8; j++) \
            _Pragma("unroll") for (int c = 0; c < 4; c++) acc[i][j][c] = 0.f; \
    const int nk = K >> 5; \
    auto load_stage = [&](int st, int kt) { \
        uint32_t sb = smbase + st * STAGE_B; \
        _Pragma("unroll") for (int i = 0; i < 4; i++) { \
            int row = (tid >> 2) + i * 32; \
            size_t g = (size_t)(by * 128 + row) * K + kt + (tid & 3) * 8; \
            cpa16(sb + AH_OFF + (uint32_t)(row * ASTR + (tid & 3) * 8) * 2, Ahg + g); \
            if (useAl) cpa16(sb + AL_OFF + (uint32_t)(row * ASTR + (tid & 3) * 8) * 2, Alg + g); \
        } \
        _Pragma("unroll") for (int i = 0; i < 4; i++) { \
            int row = (tid >> 4) + i * 8; \
            size_t g = (size_t)(kt + row) * N + bx * 128 + (tid & 15) * 8; \
            cpa16(sb + BH_OFF + (uint32_t)(row * BSTR + (tid & 15) * 8) * 2, Bhg + g); \
            if (useBl) cpa16(sb + BL_OFF + (uint32_t)(row * BSTR + (tid & 15) * 8) * 2, Blg + g); \
        } \
        cp_commit(); \
    }; \
    load_stage(0, 0); \
    load_stage(1, 32); \
    for (int i = 0; i < nk; i++) { \
        if (i + 1 < nk) cp_wait<1>(); else cp_wait<0>(); \
        __syncthreads(); \
        if (i + 2 < nk) load_stage((i + 2) % 3, (i + 2) * 32); \
        uint32_t sb = smbase + (i % 3) * STAGE_B; \
        _Pragma("unroll") for (int ks = 0; ks < 2; ks++) { \
            uint32_t ahf[4][4], alf[4][4]; \
            _Pragma("unroll") for (int mi = 0; mi < 4; mi++) { \
                uint32_t off = a_off + (uint32_t)(mi * 16 * ASTR + ks * 16) * 2; \
                ldsm_x4(ahf[mi], sb + AH_OFF + off); \
                if (useAl) ldsm_x4(alf[mi], sb + AL_OFF + off); \
            } \
            _Pragma("unroll") for (int nb = 0; nb < 2; nb++) { \
                uint32_t bhf[4][2]; \
                _Pragma("unroll") for (int nj = 0; nj < 4; nj++) { \
                    uint32_t off = b_off + (uint32_t)(ks * 16 * BSTR + (nb * 4 + nj) * 8) * 2; \
                    ldsm_x2t(bhf[nj], sb + BH_OFF + off); \
                } \
                _Pragma("unroll") for (int nj = 0; nj < 4; nj++) \
                    _Pragma("unroll") for (int mi = 0; mi < 4; mi++) \
                        mma16816(acc[mi][nb * 4 + nj], ahf[mi], bhf[nj]); \
                if (useAl) { \
                    _Pragma("unroll") for (int nj = 0; nj < 4; nj++) \
                        _Pragma("unroll") for (int mi = 0; mi < 4; mi++) \
                            mma16816(acc[mi][nb * 4 + nj], alf[mi], bhf[nj]); \
                } \
                if (useBl) { \
                    uint32_t blf[4][2]; \
                    _Pragma("unroll") for (int nj = 0; nj < 4; nj++) { \
                        uint32_t off = b_off + (uint32_t)(ks * 16 * BSTR + (nb * 4 + nj) * 8) * 2; \
                        ldsm_x2t(blf[nj], sb + BL_OFF + off); \
                    } \
                    _Pragma("unroll") for (int nj = 0; nj < 4; nj++) \
                        _Pragma("unroll") for (int mi = 0; mi < 4; mi++) \
                            mma16816(acc[mi][nb * 4 + nj], ahf[mi], blf[nj]); \
                } \
            } \
        } \
    } \
    __syncthreads();

// ---------------------------------------------------------------------------
// QKV GEMM: q,k CTAs 1-pass; v CTAs 3-pass. Stores hi-only fp16 [b,h,s,d].
// Epilogue: val = acc/WSCALE + bias (q NOT pre-scaled; QSCALE applied at scores)
// ---------------------------------------------------------------------------
__global__ __launch_bounds__(128, 2) void mma_gemm_qkv(
    const __half* __restrict__ Ahg, const __half* __restrict__ Alg,
    const __half* __restrict__ Bhg, const __half* __restrict__ Blg,
    const float* __restrict__ bias,
    __half* __restrict__ q, __half* __restrict__ k, __half* __restrict__ v,
    int M, int N, int K)
{
    GEMM_PROLOG(blockIdx.x >= 16, blockIdx.x >= 16)  // v part 3-pass; q,k 1-pass

    int part = (bx * 128) >> 10;
    __half* dst = part == 0 ? q : (part == 1 ? k : v);
    int head = ((bx * 128 + wn) & 1023) >> 6;
    int bq = (by * 128) >> 10;
    int group = lane >> 2, tig = lane & 3;
    const float inv = 1.0f / WSCALE;
    #pragma unroll
    for (int mi = 0; mi < 4; mi++) {
        int s0 = ((by * 128) & 1023) + wm + mi * 16 + group;
        #pragma unroll
        for (int ni = 0; ni < 8; ni++) {
            int col = bx * 128 + wn + ni * 8 + tig * 2;
            int d = ni * 8 + tig * 2;
            float b0 = bias[col], b1 = bias[col + 1];
            float v00 = acc[mi][ni][0] * inv + b0, v01 = acc[mi][ni][1] * inv + b1;
            float v10 = acc[mi][ni][2] * inv + b0, v11 = acc[mi][ni][3] * inv + b1;
            size_t o0 = ((size_t)(bq * HH + head) * SS + s0) * HD + d;
            size_t o1 = o0 + 8 * HD;
            *(__half2*)&dst[o0] = __halves2half2(__float2half_rn(v00), __float2half_rn(v01));
            *(__half2*)&dst[o1] = __halves2half2(__float2half_rn(v10), __float2half_rn(v11));
        }
    }
}

// ---------------------------------------------------------------------------
// Out-projection GEMM: 3-pass; val = acc/(WSCALE*AOSCALE) + bias
// ---------------------------------------------------------------------------
__global__ __launch_bounds__(128, 2) void mma_gemm_out(
    const __half* __restrict__ Ahg, const __half* __restrict__ Alg,
    const __half* __restrict__ Bhg, const __half* __restrict__ Blg,
    const float* __restrict__ bias, float* __restrict__ C,
    int M, int N, int K)
{
    GEMM_PROLOG(true, true)

    int group = lane >> 2, tig = lane & 3;
    const float inv = 1.0f / (WSCALE * AOSCALE);
    #pragma unroll
    for (int mi = 0; mi < 4; mi++) {
        int row0 = by * 128 + wm + mi * 16 + group;
        #pragma unroll
        for (int ni = 0; ni < 8; ni++) {
            int col = bx * 128 + wn + ni * 8 + tig * 2;
            float b0 = bias[col], b1 = bias[col + 1];
            *(float2*)&C[(size_t)row0 * N + col] =
                make_float2(acc[mi][ni][0] * inv + b0, acc[mi][ni][1] * inv + b1);
            *(float2*)&C[(size_t)(row0 + 8) * N + col] =
                make_float2(acc[mi][ni][2] * inv + b0, acc[mi][ni][3] * inv + b1);
        }
    }
}

// ---------------------------------------------------------------------------
// Scores + softmax: per (b,h,32q). 1-pass fp16: S = QSCALE * (qh @ kh^T).
// K-chunks of 256; 8 warps = 2m x 4n. smem: Ssc fp32[32][1032] | Q [32][72] |
// K x2 stages [256][72]
// ---------------------------------------------------------------------------
#define SC_Q   132096
#define SC_K   136704
#define SC_KSTAGE 36864
#define SC_SMEM 210432

__global__ __launch_bounds__(256) void attn_scores_mma(
    const __half* __restrict__ q, const __half* __restrict__ k,
    __half* __restrict__ Ph, __half* __restrict__ Pl)
{
    extern __shared__ char dynsm[];
    float* Ssc = (float*)dynsm;
    uint32_t smbase = (uint32_t)__cvta_generic_to_shared(dynsm);

    int b = blockIdx.z, h = blockIdx.y, q0 = blockIdx.x * 32;
    int tid = threadIdx.x, lane = tid & 31, wid = tid >> 5;
    int wm = (wid & 1) * 16;
    int wn = (wid >> 1) * 64;

    {
        size_t qb = ((size_t)(b * HH + h) * SS + q0) * HD;
        int row = tid >> 3, c8 = (tid & 7) * 8;
        *(uint4*)(dynsm + SC_Q + (row * 72 + c8) * 2) = *(const uint4*)&q[qb + row * 64 + c8];
    }

    auto load_k = [&](int st, int kt) {
        uint32_t kb = smbase + SC_K + st * SC_KSTAGE;
        size_t gb = ((size_t)(b * HH + h) * SS + kt) * HD;
        #pragma unroll
        for (int it = 0; it < 8; it++) {
            int idx = tid + it * 256;
            int row = idx >> 3, c8 = (idx & 7) * 8;
            cpa16(kb + (uint32_t)(row * 72 + c8) * 2, k + gb + (size_t)row * 64 + c8);
        }
        cp_commit();
    };
    load_k(0, 0);
    load_k(1, 256);

    uint32_t aq_off = (uint32_t)((wm + (lane & 15)) * 72 + (lane >> 4) * 8) * 2;
    int rr_ = lane & 7, halfk = (lane >> 3) & 1, q2 = lane >> 4;

    for (int i = 0; i < 4; i++) {
        if (i < 3) cp_wait<1>(); else cp_wait<0>();
        __syncthreads();
        uint32_t kb = smbase + SC_K + (i & 1) * SC_KSTAGE;

        float acc[8][4];
        #pragma unroll
        for (int a = 0; a < 8; a++)
            #pragma unroll
            for (int c = 0; c < 4; c++) acc[a][c] = 0.f;

        #pragma unroll
        for (int ks = 0; ks < 4; ks++) {
            uint32_t ahf[4];
            ldsm_x4(ahf, smbase + SC_Q + aq_off + ks * 32);
            uint32_t bhf[4][4];
            #pragma unroll
            for (int nb = 0; nb < 4; nb++) {
                uint32_t boff = (uint32_t)((wn + nb * 16 + q2 * 8 + rr_) * 72 + halfk * 8 + ks * 16) * 2;
                ldsm_x4(bhf[nb], kb + boff);
            }
            #pragma unroll
            for (int nb = 0; nb < 4; nb++) {
                mma16816(acc[nb*2],   ahf, bhf[nb]);
                mma16816(acc[nb*2+1], ahf, bhf[nb] + 2);
            }
        }

        int kt = i * 256;
        int group = lane >> 2, tig = lane & 3;
        #pragma unroll
        for (int ni = 0; ni < 8; ni++) {
            int row = wm + group;
            int col = kt + wn + ni * 8 + tig * 2;
            *(float2*)&Ssc[row * 1032 + col] =
                make_float2(acc[ni][0] * QSCALE, acc[ni][1] * QSCALE);
            *(float2*)&Ssc[(row + 8) * 1032 + col] =
                make_float2(acc[ni][2] * QSCALE, acc[ni][3] * QSCALE);
        }
        __syncthreads();
        if (i + 2 < 4) load_k((i + 2) & 1, (i + 2) * 256);
    }

    for (int rr = 0; rr < 4; rr++) {
        int row = wid * 4 + rr;
        float2 v2[16];
        float m = -1e30f;
        #pragma unroll
        for (int i2 = 0; i2 < 16; i2++) {
            v2[i2] = *(float2*)&Ssc[row * 1032 + (lane + i2 * 32) * 2];
            m = fmaxf(m, fmaxf(v2[i2].x, v2[i2].y));
        }
        #pragma unroll
        for (int o = 16; o; o >>= 1) m = fmaxf(m, __shfl_xor_sync(0xffffffffu, m, o));
        float s = 0.f;
        #pragma unroll
        for (int i2 = 0; i2 < 16; i2++) {
            v2[i2].x = __expf(v2[i2].x - m);
            v2[i2].y = __expf(v2[i2].y - m);
            s += v2[i2].x + v2[i2].y;
        }
        #pragma unroll
        for (int o = 16; o; o >>= 1) s += __shfl_xor_sync(0xffffffffu, s, o);
        float inv = 1.f / s;
        size_t gb = ((size_t)(b * HH + h) * SS + q0 + row) * SS;
        #pragma unroll
        for (int i2 = 0; i2 < 16; i2++) {
            float p0 = v2[i2].x * inv, p1 = v2[i2].y * inv;
            __half h0, l0, h1, l1;
            split_fp16(p0, h0, l0); split_fp16(p1, h1, l1);
            size_t o = gb + (size_t)(lane + i2 * 32) * 2;
            *(__half2*)&Ph[o] = __halves2half2(h0, h1);
            *(__half2*)&Pl[o] = __halves2half2(l0, l1);
        }
    }
}

// ---------------------------------------------------------------------------
// PV: AO = P @ V per (b,h,256q). 2-pass fp16: (Ph + Pl) @ vh.
// 8 warps x (32q x 64d). AO stored x16 as fp16 split.
// smem x2 stages: Ph [256][72] + Pl [256][72] + Vh [64][72]
// ---------------------------------------------------------------------------
#define PV_PH 0
#define PV_PL 36864
#define PV_VH 73728
#define PV_STAGE 82944
#define PV_SMEM 165888

__global__ __launch_bounds__(256) void attn_pv_mma(
    const __half* __restrict__ Ph, const __half* __restrict__ Pl,
    const __half* __restrict__ v,
    __half* __restrict__ AOh, __half* __restrict__ AOl)
{
    extern __shared__ char dynsm[];
    uint32_t smbase = (uint32_t)__cvta_generic_to_shared(dynsm);

    int b = blockIdx.z, h = blockIdx.y, q0 = blockIdx.x * 256;
    int tid = threadIdx.x, lane = tid & 31, wid = tid >> 5;

    auto load_stage = [&](int st, int kt) {
        uint32_t sb = smbase + st * PV_STAGE;
        size_t pb = ((size_t)(b * HH + h) * SS + q0) * SS + kt;
        #pragma unroll
        for (int it = 0; it < 8; it++) {
            int idx = tid + it * 256;
            int row = idx >> 3, c8 = (idx & 7) * 8;
            cpa16(sb + PV_PH + (uint32_t)(row * 72 + c8) * 2, Ph + pb + (size_t)row * SS + c8);
            cpa16(sb + PV_PL + (uint32_t)(row * 72 + c8) * 2, Pl + pb + (size_t)row * SS + c8);
        }
        size_t vb = ((size_t)(b * HH + h) * SS + kt) * HD;
        #pragma unroll
        for (int it = 0; it < 2; it++) {
            int idx = tid + it * 256;
            int row = idx >> 3, c8 = (idx & 7) * 8;
            cpa16(sb + PV_VH + (uint32_t)(row * 72 + c8) * 2, v + vb + row * 64 + c8);
        }
        cp_commit();
    };

    float acc[2][8][4];
    #pragma unroll
    for (int a = 0; a < 2; a++)
        #pragma unroll
        for (int j = 0; j < 8; j++)
            #pragma unroll
            for (int c = 0; c < 4; c++) acc[a][j][c] = 0.f;

    uint32_t ap_off = (uint32_t)((wid * 32 + (lane & 15)) * 72 + (lane >> 4) * 8) * 2;
    uint32_t bv_off = (uint32_t)((lane & 15) * 72) * 2;

    load_stage(0, 0);
    load_stage(1, 64);

    for (int i = 0; i < 16; i++) {
        if (i < 15) cp_wait<1>(); else cp_wait<0>();
        __syncthreads();
        uint32_t sb = smbase + (i & 1) * PV_STAGE;
        #pragma unroll
        for (int ks = 0; ks < 4; ks++) {
            uint32_t ahf[2][4], alf[2][4];
            #pragma unroll
            for (int mi = 0; mi < 2; mi++) {
                uint32_t off = ap_off + (uint32_t)(mi * 16 * 72 + ks * 16) * 2;
                ldsm_x4(ahf[mi], sb + PV_PH + off);
                ldsm_x4(alf[mi], sb + PV_PL + off);
            }
            #pragma unroll
            for (int nb = 0; nb < 2; nb++) {
                uint32_t bhf[4][2];
                #pragma unroll
                for (int nj = 0; nj < 4; nj++) {
                    uint32_t off = bv_off + (uint32_t)(ks * 16 * 72 + (nb * 4 + nj) * 8) * 2;
                    ldsm_x2t(bhf[nj], sb + PV_VH + off);
                }
                #pragma unroll
                for (int nj = 0; nj < 4; nj++)
                    #pragma unroll
                    for (int mi = 0; mi < 2; mi++)
                        mma16816(acc[mi][nb*4+nj], ahf[mi], bhf[nj]);
                #pragma unroll
                for (int nj = 0; nj < 4; nj++)
                    #pragma unroll
                    for (int mi = 0; mi < 2; mi++)
                        mma16816(acc[mi][nb*4+nj], alf[mi], bhf[nj]);
            }
        }
        __syncthreads();
        if (i + 2 < 16) load_stage((i + 2) & 1, (i + 2) * 64);
    }

    int group = lane >> 2, tig = lane & 3;
    #pragma unroll
    for (int mi = 0; mi < 2; mi++) {
        #pragma unroll
        for (int ni = 0; ni < 8; ni++) {
            int d = ni * 8 + tig * 2;
            int r0 = q0 + wid * 32 + mi * 16 + group;
            size_t o0 = (size_t)(b * SS + r0) * DD + h * HD + d;
            size_t o1 = o0 + (size_t)8 * DD;
            __half h0, l0, h1, l1;
            split_fp16(acc[mi][ni][0] * AOSCALE, h0, l0);
            split_fp16(acc[mi][ni][1] * AOSCALE, h1, l1);
            *(__half2*)&AOh[o0] = __halves2half2(h0, h1);
            *(__half2*)&AOl[o0] = __halves2half2(l0, l1);
            split_fp16(acc[mi][ni][2] * AOSCALE, h0, l0);
            split_fp16(acc[mi][ni][3] * AOSCALE, h1, l1);
            *(__half2*)&AOh[o1] = __halves2half2(h0, h1);
            *(__half2*)&AOl[o1] = __halves2half2(l0, l1);
        }
    }
}

// ---------------------------------------------------------------------------
// attn_mean[b,q,k] = (1/H) * sum_h (Ph + Pl)
// ---------------------------------------------------------------------------
__global__ __launch_bounds__(256) void attn_mean_kernel(
    const __half* __restrict__ Ph, const __half* __restrict__ Pl,
    float* __restrict__ outm)
{
    size_t g = (size_t)blockIdx.x * 256 + threadIdx.x;
    int k8 = (int)(g & 127);
    size_t t = g >> 7;
    int q = (int)(t & 1023);
    int b = (int)(t >> 10);
    size_t k = (size_t)k8 * 8;

    float acc8[8];
    #pragma unroll
    for (int j = 0; j < 8; j++) acc8[j] = 0.f;
    #pragma unroll
    for (int h = 0; h < HH; h++) {
        size_t off = ((size_t)(b * HH + h) * SS + q) * SS + k;
        uint4 vh4 = *(const uint4*)&Ph[off];
        uint4 vl4 = *(const uint4*)&Pl[off];
        const uint32_t* ph = (const uint32_t*)&vh4;
        const uint32_t* pl = (const uint32_t*)&vl4;
        #pragma unroll
        for (int j = 0; j < 4; j++) {
            float2 hh = __half22float2(*(__half2*)&ph[j]);
            float2 ll = __half22float2(*(__half2*)&pl[j]);
            acc8[2*j]   += hh.x + ll.x;
            acc8[2*j+1] += hh.y + ll.y;
        }
    }
    size_t ob = ((size_t)(b * SS + q)) * SS + k;
    const float inv = 1.0f / HH;
    float4 o0 = make_float4(acc8[0]*inv, acc8[1]*inv, acc8[2]*inv, acc8[3]*inv);
    float4 o1 = make_float4(acc8[4]*inv, acc8[5]*inv, acc8[6]*inv, acc8[7]*inv);
    *(float4*)&outm[ob]     = o0;
    *(float4*)&outm[ob + 4] = o1;
}

// ---------------------------------------------------------------------------
// Host launcher (fork-join: attn_mean overlaps PV + out-proj)
// ---------------------------------------------------------------------------
extern "C" void kernel_launch(void* const* d_in, const int* in_sizes, int n_in,
                              void* d_out, int out_size)
{
    const float* x     = (const float*)d_in[0];
    const float* w_in  = (const float*)d_in[1];
    const float* b_in  = (const float*)d_in[2];
    const float* w_out = (const float*)d_in[3];
    const float* b_out = (const float*)d_in[4];
    float* out = (float*)d_out;

    __half *xh, *xl, *wih, *wil, *woh, *wol;
    __half *q, *k, *v, *ph, *pl, *aoh, *aol;
    cudaGetSymbolAddress((void**)&xh,  g_xh);
    cudaGetSymbolAddress((void**)&xl,  g_xl);
    cudaGetSymbolAddress((void**)&wih, g_wih);
    cudaGetSymbolAddress((void**)&wil, g_wil);
    cudaGetSymbolAddress((void**)&woh, g_woh);
    cudaGetSymbolAddress((void**)&wol, g_wol);
    cudaGetSymbolAddress((void**)&q,   g_q);
    cudaGetSymbolAddress((void**)&k,   g_k);
    cudaGetSymbolAddress((void**)&v,   g_v);
    cudaGetSymbolAddress((void**)&ph,  g_ph);
    cudaGetSymbolAddress((void**)&pl,  g_pl);
    cudaGetSymbolAddress((void**)&aoh, g_aoh);
    cudaGetSymbolAddress((void**)&aol, g_aol);

    static cudaStream_t s1 = nullptr;
    static cudaEvent_t evA = nullptr, evB = nullptr;
    if (!s1) {
        cudaStreamCreateWithFlags(&s1, cudaStreamNonBlocking);
        cudaEventCreateWithFlags(&evA, cudaEventDisableTiming);
        cudaEventCreateWithFlags(&evB, cudaEventDisableTiming);
    }

    cudaFuncSetAttribute(mma_gemm_qkv,
                         cudaFuncAttributeMaxDynamicSharedMemorySize, GEMM_SMEM);
    cudaFuncSetAttribute(mma_gemm_out,
                         cudaFuncAttributeMaxDynamicSharedMemorySize, GEMM_SMEM);
    cudaFuncSetAttribute(attn_scores_mma,
                         cudaFuncAttributeMaxDynamicSharedMemorySize, SC_SMEM);
    cudaFuncSetAttribute(attn_pv_mma,
                         cudaFuncAttributeMaxDynamicSharedMemorySize, PV_SMEM);

    // 0. pre-split inputs (weights pre-scaled x64 to keep fp16 lo normal)
    split_kernel<<<(MROWS * DD / 4 + 255) / 256, 256>>>(x, xh, xl, 1.0f, MROWS * DD / 4);
    split_kernel<<<(DD * 3 * DD / 4 + 255) / 256, 256>>>(w_in, wih, wil, WSCALE, DD * 3 * DD / 4);
    split_kernel<<<(DD * DD / 4 + 255) / 256, 256>>>(w_out, woh, wol, WSCALE, DD * DD / 4);

    // 1. QKV GEMM -> fp16 q/k/v per head (q,k 1-pass; v 3-pass)
    mma_gemm_qkv<<<dim3(3 * DD / 128, MROWS / 128), 128, GEMM_SMEM>>>(
        xh, xl, wih, wil, b_in, q, k, v, MROWS, 3 * DD, DD);

    // 2. scores (1-pass, QSCALE fused) + softmax -> fp16 split P
    attn_scores_mma<<<dim3(SS / 32, HH, BB), 256, SC_SMEM>>>(q, k, ph, pl);

    // fork: head-mean (DRAM-bound) on side stream, overlapping PV + out-proj
    cudaEventRecord(evA, 0);
    cudaStreamWaitEvent(s1, evA, 0);
    attn_mean_kernel<<<(BB * SS * SS / 8) / 256, 256, 0, s1>>>(
        ph, pl, out + (size_t)BB * SS * SS);
    cudaEventRecord(evB, s1);

    // 3. P @ V (2-pass fp16) -> fp16 split AO (x16)
    attn_pv_mma<<<dim3(SS / 256, HH, BB), 256, PV_SMEM>>>(ph, pl, v, aoh, aol);

    // 5. output projection (3-pass)
    mma_gemm_out<<<dim3(DD / 128, MROWS / 128), 128, GEMM_SMEM>>>(
        aoh, aol, woh, wol, b_out, out, MROWS, DD, DD);

    // join
    cudaStreamWaitEvent(0, evB, 0);
}

// round 12
// speedup vs baseline: 1.4009x; 1.2637x over previous
#include <cuda_runtime.h>
#include <cuda_fp16.h>
#include <cstdint>

// Problem constants
#define BB 4
#define SS 1024
#define DD 1024
#define HH 16
#define HD 64
#define MROWS (BB*SS)          // 4096
#define QSCALE 0.03125f        // 1024^-0.5 (exact power of 2)
#define WSCALE 64.0f           // weight pre-scale (keeps fp16 lo out of subnormals)
#define AOSCALE 16.0f          // AO pre-scale

// ---------------------------------------------------------------------------
// Scratch (fp16; P and AO stored hi-only)
// ---------------------------------------------------------------------------
__device__ __half g_xh[(size_t)MROWS * DD],   g_xl[(size_t)MROWS * DD];
__device__ __half g_wih[(size_t)DD * 3 * DD], g_wil[(size_t)DD * 3 * DD];  // 64*w_in
__device__ __half g_woh[(size_t)DD * DD],     g_wol[(size_t)DD * DD];      // 64*w_out
__device__ __half g_q[(size_t)BB*HH*SS*HD];
__device__ __half g_k[(size_t)BB*HH*SS*HD];
__device__ __half g_v[(size_t)BB*HH*SS*HD];
__device__ __half g_p[(size_t)BB*HH*SS*SS];                                 // hi-only P
__device__ __half g_ao[(size_t)MROWS * DD];                                 // hi-only 16*AO

// ---------------------------------------------------------------------------
// MMA / ldmatrix / cp.async helpers (fp16)
// ---------------------------------------------------------------------------
__device__ __forceinline__ void mma16816(float* d, const uint32_t* a, const uint32_t* b) {
    asm volatile(
        "mma.sync.aligned.m16n8k16.row.col.f32.f16.f16.f32 "
        "{%0,%1,%2,%3}, {%4,%5,%6,%7}, {%8,%9}, {%0,%1,%2,%3};"
        : "+f"(d[0]), "+f"(d[1]), "+f"(d[2]), "+f"(d[3])
        : "r"(a[0]), "r"(a[1]), "r"(a[2]), "r"(a[3]), "r"(b[0]), "r"(b[1]));
}
__device__ __forceinline__ void ldsm_x4(uint32_t* r, uint32_t addr) {
    asm volatile("ldmatrix.sync.aligned.m8n8.x4.shared.b16 {%0,%1,%2,%3}, [%4];"
                 : "=r"(r[0]), "=r"(r[1]), "=r"(r[2]), "=r"(r[3]) : "r"(addr));
}
__device__ __forceinline__ void ldsm_x2t(uint32_t* r, uint32_t addr) {
    asm volatile("ldmatrix.sync.aligned.m8n8.x2.trans.shared.b16 {%0,%1}, [%2];"
                 : "=r"(r[0]), "=r"(r[1]) : "r"(addr));
}
__device__ __forceinline__ void split_fp16(float v, __half& h, __half& l) {
    h = __float2half_rn(v);
    l = __float2half_rn(v - __half2float(h));
}
__device__ __forceinline__ void cpa16(uint32_t s, const void* g) {
    asm volatile("cp.async.cg.shared.global [%0], [%1], 16;" :: "r"(s), "l"(g));
}
__device__ __forceinline__ void cp_commit() { asm volatile("cp.async.commit_group;"); }
template<int N> __device__ __forceinline__ void cp_wait() {
    asm volatile("cp.async.wait_group %0;" :: "n"(N));
}

// ---------------------------------------------------------------------------
// split kernel: fp32 -> (hi, lo) fp16, with pre-scale
// ---------------------------------------------------------------------------
__global__ __launch_bounds__(256) void split_kernel(
    const float* __restrict__ in, __half* __restrict__ hi,
    __half* __restrict__ lo, float scale, int n4)
{
    int i = blockIdx.x * 256 + threadIdx.x;
    if (i >= n4) return;
    float4 v = ((const float4*)in)[i];
    __half h0, l0, h1, l1, h2, l2, h3, l3;
    split_fp16(v.x * scale, h0, l0); split_fp16(v.y * scale, h1, l1);
    split_fp16(v.z * scale, h2, l2); split_fp16(v.w * scale, h3, l3);
    ((__half2*)hi)[2 * i]     = __halves2half2(h0, h1);
    ((__half2*)hi)[2 * i + 1] = __halves2half2(h2, h3);
    ((__half2*)lo)[2 * i]     = __halves2half2(l0, l1);
    ((__half2*)lo)[2 * i + 1] = __halves2half2(l2, l3);
}

// ---------------------------------------------------------------------------
// GEMM tile (BM=BN=128, BK=32): 4 warps, warp tile 64x64.
// 3-stage cp.async pipeline. useAl: add al*bh; useBl: add ah*bl.
// ---------------------------------------------------------------------------
#define ASTR 40
#define BSTR 136
#define AH_OFF 0
#define AL_OFF 10240
#define BH_OFF 20480
#define BL_OFF 29184
#define STAGE_B 37888
#define GEMM_SMEM (STAGE_B * 3)

#define GEMM_PROLOG(useAlExpr, useBlExpr) \
    extern __shared__ char dynsm[]; \
    uint32_t smbase = (uint32_t)__cvta_generic_to_shared(dynsm); \
    int bx = blockIdx.x, by = blockIdx.y; \
    int tid = threadIdx.x, lane = tid & 31, wid = tid >> 5; \
    int wm = (wid & 1) * 64, wn = (wid >> 1) * 64; \
    const bool useAl = (useAlExpr), useBl = (useBlExpr); \
    uint32_t a_off = (uint32_t)((wm + (lane & 15)) * ASTR + (lane >> 4) * 8) * 2; \
    uint32_t b_off = (uint32_t)((lane & 15) * BSTR + wn) * 2; \
    float acc[4][8][4]; \
    _Pragma("unroll") for (int i = 0; i < 4; i++) \
        _Pragma("unroll") for (int j = 0; j < 8; j++) \
            _Pragma("unroll") for (int c = 0; c < 4; c++) acc[i][j][c] = 0.f; \
    const int nk = K >> 5; \
    auto load_stage = [&](int st, int kt) { \
        uint32_t sb = smbase + st * STAGE_B; \
        _Pragma("unroll") for (int i = 0; i < 4; i++) { \
            int row = (tid >> 2) + i * 32; \
            size_t g = (size_t)(by * 128 + row) * K + kt + (tid & 3) * 8; \
            cpa16(sb + AH_OFF + (uint32_t)(row * ASTR + (tid & 3) * 8) * 2, Ahg + g); \
            if (useAl) cpa16(sb + AL_OFF + (uint32_t)(row * ASTR + (tid & 3) * 8) * 2, Alg + g); \
        } \
        _Pragma("unroll") for (int i = 0; i < 4; i++) { \
            int row = (tid >> 4) + i * 8; \
            size_t g = (size_t)(kt + row) * N + bx * 128 + (tid & 15) * 8; \
            cpa16(sb + BH_OFF + (uint32_t)(row * BSTR + (tid & 15) * 8) * 2, Bhg + g); \
            if (useBl) cpa16(sb + BL_OFF + (uint32_t)(row * BSTR + (tid & 15) * 8) * 2, Blg + g); \
        } \
        cp_commit(); \
    }; \
    load_stage(0, 0); \
    load_stage(1, 32); \
    for (int i = 0; i < nk; i++) { \
        if (i + 1 < nk) cp_wait<1>(); else cp_wait<0>(); \
        __syncthreads(); \
        if (i + 2 < nk) load_stage((i + 2) % 3, (i + 2) * 32); \
        uint32_t sb = smbase + (i % 3) * STAGE_B; \
        _Pragma("unroll") for (int ks = 0; ks < 2; ks++) { \
            uint32_t ahf[4][4], alf[4][4]; \
            _Pragma("unroll") for (int mi = 0; mi < 4; mi++) { \
                uint32_t off = a_off + (uint32_t)(mi * 16 * ASTR + ks * 16) * 2; \
                ldsm_x4(ahf[mi], sb + AH_OFF + off); \
                if (useAl) ldsm_x4(alf[mi], sb + AL_OFF + off); \
            } \
            _Pragma("unroll") for (int nb = 0; nb < 2; nb++) { \
                uint32_t bhf[4][2]; \
                _Pragma("unroll") for (int nj = 0; nj < 4; nj++) { \
                    uint32_t off = b_off + (uint32_t)(ks * 16 * BSTR + (nb * 4 + nj) * 8) * 2; \
                    ldsm_x2t(bhf[nj], sb + BH_OFF + off); \
                } \
                _Pragma("unroll") for (int nj = 0; nj < 4; nj++) \
                    _Pragma("unroll") for (int mi = 0; mi < 4; mi++) \
                        mma16816(acc[mi][nb * 4 + nj], ahf[mi], bhf[nj]); \
                if (useAl) { \
                    _Pragma("unroll") for (int nj = 0; nj < 4; nj++) \
                        _Pragma("unroll") for (int mi = 0; mi < 4; mi++) \
                            mma16816(acc[mi][nb * 4 + nj], alf[mi], bhf[nj]); \
                } \
                if (useBl) { \
                    uint32_t blf[4][2]; \
                    _Pragma("unroll") for (int nj = 0; nj < 4; nj++) { \
                        uint32_t off = b_off + (uint32_t)(ks * 16 * BSTR + (nb * 4 + nj) * 8) * 2; \
                        ldsm_x2t(blf[nj], sb + BL_OFF + off); \
                    } \
                    _Pragma("unroll") for (int nj = 0; nj < 4; nj++) \
                        _Pragma("unroll") for (int mi = 0; mi < 4; mi++) \
                            mma16816(acc[mi][nb * 4 + nj], ahf[mi], blf[nj]); \
                } \
            } \
        } \
    } \
    __syncthreads();

// ---------------------------------------------------------------------------
// QKV GEMM: q,k CTAs 1-pass; v CTAs 3-pass. Stores hi-only fp16 [b,h,s,d].
// ---------------------------------------------------------------------------
__global__ __launch_bounds__(128, 2) void mma_gemm_qkv(
    const __half* __restrict__ Ahg, const __half* __restrict__ Alg,
    const __half* __restrict__ Bhg, const __half* __restrict__ Blg,
    const float* __restrict__ bias,
    __half* __restrict__ q, __half* __restrict__ k, __half* __restrict__ v,
    int M, int N, int K)
{
    GEMM_PROLOG(blockIdx.x >= 16, blockIdx.x >= 16)  // v part 3-pass; q,k 1-pass

    int part = (bx * 128) >> 10;
    __half* dst = part == 0 ? q : (part == 1 ? k : v);
    int head = ((bx * 128 + wn) & 1023) >> 6;
    int bq = (by * 128) >> 10;
    int group = lane >> 2, tig = lane & 3;
    const float inv = 1.0f / WSCALE;
    #pragma unroll
    for (int mi = 0; mi < 4; mi++) {
        int s0 = ((by * 128) & 1023) + wm + mi * 16 + group;
        #pragma unroll
        for (int ni = 0; ni < 8; ni++) {
            int col = bx * 128 + wn + ni * 8 + tig * 2;
            int d = ni * 8 + tig * 2;
            float b0 = bias[col], b1 = bias[col + 1];
            float v00 = acc[mi][ni][0] * inv + b0, v01 = acc[mi][ni][1] * inv + b1;
            float v10 = acc[mi][ni][2] * inv + b0, v11 = acc[mi][ni][3] * inv + b1;
            size_t o0 = ((size_t)(bq * HH + head) * SS + s0) * HD + d;
            size_t o1 = o0 + 8 * HD;
            *(__half2*)&dst[o0] = __halves2half2(__float2half_rn(v00), __float2half_rn(v01));
            *(__half2*)&dst[o1] = __halves2half2(__float2half_rn(v10), __float2half_rn(v11));
        }
    }
}

// ---------------------------------------------------------------------------
// Out-projection GEMM: 2-pass (AO hi-only): ah*bh + ah*bl.
// val = acc/(WSCALE*AOSCALE) + bias
// ---------------------------------------------------------------------------
__global__ __launch_bounds__(128, 2) void mma_gemm_out(
    const __half* __restrict__ Ahg, const __half* __restrict__ Alg,
    const __half* __restrict__ Bhg, const __half* __restrict__ Blg,
    const float* __restrict__ bias, float* __restrict__ C,
    int M, int N, int K)
{
    GEMM_PROLOG(false, true)

    int group = lane >> 2, tig = lane & 3;
    const float inv = 1.0f / (WSCALE * AOSCALE);
    #pragma unroll
    for (int mi = 0; mi < 4; mi++) {
        int row0 = by * 128 + wm + mi * 16 + group;
        #pragma unroll
        for (int ni = 0; ni < 8; ni++) {
            int col = bx * 128 + wn + ni * 8 + tig * 2;
            float b0 = bias[col], b1 = bias[col + 1];
            *(float2*)&C[(size_t)row0 * N + col] =
                make_float2(acc[mi][ni][0] * inv + b0, acc[mi][ni][1] * inv + b1);
            *(float2*)&C[(size_t)(row0 + 8) * N + col] =
                make_float2(acc[mi][ni][2] * inv + b0, acc[mi][ni][3] * inv + b1);
        }
    }
}

// ---------------------------------------------------------------------------
// Scores + softmax: per (b,h,32q). 1-pass fp16: S = QSCALE * (q @ k^T).
// P written hi-only.
// ---------------------------------------------------------------------------
#define SC_Q   132096
#define SC_K   136704
#define SC_KSTAGE 36864
#define SC_SMEM 210432

__global__ __launch_bounds__(256) void attn_scores_mma(
    const __half* __restrict__ q, const __half* __restrict__ k,
    __half* __restrict__ P)
{
    extern __shared__ char dynsm[];
    float* Ssc = (float*)dynsm;
    uint32_t smbase = (uint32_t)__cvta_generic_to_shared(dynsm);

    int b = blockIdx.z, h = blockIdx.y, q0 = blockIdx.x * 32;
    int tid = threadIdx.x, lane = tid & 31, wid = tid >> 5;
    int wm = (wid & 1) * 16;
    int wn = (wid >> 1) * 64;

    {
        size_t qb = ((size_t)(b * HH + h) * SS + q0) * HD;
        int row = tid >> 3, c8 = (tid & 7) * 8;
        *(uint4*)(dynsm + SC_Q + (row * 72 + c8) * 2) = *(const uint4*)&q[qb + row * 64 + c8];
    }

    auto load_k = [&](int st, int kt) {
        uint32_t kb = smbase + SC_K + st * SC_KSTAGE;
        size_t gb = ((size_t)(b * HH + h) * SS + kt) * HD;
        #pragma unroll
        for (int it = 0; it < 8; it++) {
            int idx = tid + it * 256;
            int row = idx >> 3, c8 = (idx & 7) * 8;
            cpa16(kb + (uint32_t)(row * 72 + c8) * 2, k + gb + (size_t)row * 64 + c8);
        }
        cp_commit();
    };
    load_k(0, 0);
    load_k(1, 256);

    uint32_t aq_off = (uint32_t)((wm + (lane & 15)) * 72 + (lane >> 4) * 8) * 2;
    int rr_ = lane & 7, halfk = (lane >> 3) & 1, q2 = lane >> 4;

    for (int i = 0; i < 4; i++) {
        if (i < 3) cp_wait<1>(); else cp_wait<0>();
        __syncthreads();
        uint32_t kb = smbase + SC_K + (i & 1) * SC_KSTAGE;

        float acc[8][4];
        #pragma unroll
        for (int a = 0; a < 8; a++)
            #pragma unroll
            for (int c = 0; c < 4; c++) acc[a][c] = 0.f;

        #pragma unroll
        for (int ks = 0; ks < 4; ks++) {
            uint32_t ahf[4];
            ldsm_x4(ahf, smbase + SC_Q + aq_off + ks * 32);
            uint32_t bhf[4][4];
            #pragma unroll
            for (int nb = 0; nb < 4; nb++) {
                uint32_t boff = (uint32_t)((wn + nb * 16 + q2 * 8 + rr_) * 72 + halfk * 8 + ks * 16) * 2;
                ldsm_x4(bhf[nb], kb + boff);
            }
            #pragma unroll
            for (int nb = 0; nb < 4; nb++) {
                mma16816(acc[nb*2],   ahf, bhf[nb]);
                mma16816(acc[nb*2+1], ahf, bhf[nb] + 2);
            }
        }

        int kt = i * 256;
        int group = lane >> 2, tig = lane & 3;
        #pragma unroll
        for (int ni = 0; ni < 8; ni++) {
            int row = wm + group;
            int col = kt + wn + ni * 8 + tig * 2;
            *(float2*)&Ssc[row * 1032 + col] =
                make_float2(acc[ni][0] * QSCALE, acc[ni][1] * QSCALE);
            *(float2*)&Ssc[(row + 8) * 1032 + col] =
                make_float2(acc[ni][2] * QSCALE, acc[ni][3] * QSCALE);
        }
        __syncthreads();
        if (i + 2 < 4) load_k((i + 2) & 1, (i + 2) * 256);
    }

    for (int rr = 0; rr < 4; rr++) {
        int row = wid * 4 + rr;
        float2 v2[16];
        float m = -1e30f;
        #pragma unroll
        for (int i2 = 0; i2 < 16; i2++) {
            v2[i2] = *(float2*)&Ssc[row * 1032 + (lane + i2 * 32) * 2];
            m = fmaxf(m, fmaxf(v2[i2].x, v2[i2].y));
        }
        #pragma unroll
        for (int o = 16; o; o >>= 1) m = fmaxf(m, __shfl_xor_sync(0xffffffffu, m, o));
        float s = 0.f;
        #pragma unroll
        for (int i2 = 0; i2 < 16; i2++) {
            v2[i2].x = __expf(v2[i2].x - m);
            v2[i2].y = __expf(v2[i2].y - m);
            s += v2[i2].x + v2[i2].y;
        }
        #pragma unroll
        for (int o = 16; o; o >>= 1) s += __shfl_xor_sync(0xffffffffu, s, o);
        float inv = 1.f / s;
        size_t gb = ((size_t)(b * HH + h) * SS + q0 + row) * SS;
        #pragma unroll
        for (int i2 = 0; i2 < 16; i2++) {
            size_t o = gb + (size_t)(lane + i2 * 32) * 2;
            *(__half2*)&P[o] = __halves2half2(
                __float2half_rn(v2[i2].x * inv), __float2half_rn(v2[i2].y * inv));
        }
    }
}

// ---------------------------------------------------------------------------
// PV: AO = P @ V per (b,h,256q). 1-pass fp16 (P hi-only).
// 8 warps x (32q x 64d). AO stored x16 hi-only.
// smem x2 stages: P [256][72] + Vh [64][72]
// ---------------------------------------------------------------------------
#define PV_P  0
#define PV_VH 36864
#define PV_STAGE 46080
#define PV_SMEM 92160

__global__ __launch_bounds__(256) void attn_pv_mma(
    const __half* __restrict__ P, const __half* __restrict__ v,
    __half* __restrict__ AO)
{
    extern __shared__ char dynsm[];
    uint32_t smbase = (uint32_t)__cvta_generic_to_shared(dynsm);

    int b = blockIdx.z, h = blockIdx.y, q0 = blockIdx.x * 256;
    int tid = threadIdx.x, lane = tid & 31, wid = tid >> 5;

    auto load_stage = [&](int st, int kt) {
        uint32_t sb = smbase + st * PV_STAGE;
        size_t pb = ((size_t)(b * HH + h) * SS + q0) * SS + kt;
        #pragma unroll
        for (int it = 0; it < 8; it++) {
            int idx = tid + it * 256;
            int row = idx >> 3, c8 = (idx & 7) * 8;
            cpa16(sb + PV_P + (uint32_t)(row * 72 + c8) * 2, P + pb + (size_t)row * SS + c8);
        }
        size_t vb = ((size_t)(b * HH + h) * SS + kt) * HD;
        #pragma unroll
        for (int it = 0; it < 2; it++) {
            int idx = tid + it * 256;
            int row = idx >> 3, c8 = (idx & 7) * 8;
            cpa16(sb + PV_VH + (uint32_t)(row * 72 + c8) * 2, v + vb + row * 64 + c8);
        }
        cp_commit();
    };

    float acc[2][8][4];
    #pragma unroll
    for (int a = 0; a < 2; a++)
        #pragma unroll
        for (int j = 0; j < 8; j++)
            #pragma unroll
            for (int c = 0; c < 4; c++) acc[a][j][c] = 0.f;

    uint32_t ap_off = (uint32_t)((wid * 32 + (lane & 15)) * 72 + (lane >> 4) * 8) * 2;
    uint32_t bv_off = (uint32_t)((lane & 15) * 72) * 2;

    load_stage(0, 0);
    load_stage(1, 64);

    for (int i = 0; i < 16; i++) {
        if (i < 15) cp_wait<1>(); else cp_wait<0>();
        __syncthreads();
        uint32_t sb = smbase + (i & 1) * PV_STAGE;
        #pragma unroll
        for (int ks = 0; ks < 4; ks++) {
            uint32_t ahf[2][4];
            #pragma unroll
            for (int mi = 0; mi < 2; mi++) {
                uint32_t off = ap_off + (uint32_t)(mi * 16 * 72 + ks * 16) * 2;
                ldsm_x4(ahf[mi], sb + PV_P + off);
            }
            #pragma unroll
            for (int nb = 0; nb < 2; nb++) {
                uint32_t bhf[4][2];
                #pragma unroll
                for (int nj = 0; nj < 4; nj++) {
                    uint32_t off = bv_off + (uint32_t)(ks * 16 * 72 + (nb * 4 + nj) * 8) * 2;
                    ldsm_x2t(bhf[nj], sb + PV_VH + off);
                }
                #pragma unroll
                for (int nj = 0; nj < 4; nj++)
                    #pragma unroll
                    for (int mi = 0; mi < 2; mi++)
                        mma16816(acc[mi][nb*4+nj], ahf[mi], bhf[nj]);
            }
        }
        __syncthreads();
        if (i + 2 < 16) load_stage((i + 2) & 1, (i + 2) * 64);
    }

    int group = lane >> 2, tig = lane & 3;
    #pragma unroll
    for (int mi = 0; mi < 2; mi++) {
        #pragma unroll
        for (int ni = 0; ni < 8; ni++) {
            int d = ni * 8 + tig * 2;
            int r0 = q0 + wid * 32 + mi * 16 + group;
            size_t o0 = (size_t)(b * SS + r0) * DD + h * HD + d;
            size_t o1 = o0 + (size_t)8 * DD;
            *(__half2*)&AO[o0] = __halves2half2(
                __float2half_rn(acc[mi][ni][0] * AOSCALE),
                __float2half_rn(acc[mi][ni][1] * AOSCALE));
            *(__half2*)&AO[o1] = __halves2half2(
                __float2half_rn(acc[mi][ni][2] * AOSCALE),
                __float2half_rn(acc[mi][ni][3] * AOSCALE));
        }
    }
}

// ---------------------------------------------------------------------------
// attn_mean[b,q,k] = (1/H) * sum_h P  (P hi-only)
// ---------------------------------------------------------------------------
__global__ __launch_bounds__(256) void attn_mean_kernel(
    const __half* __restrict__ P, float* __restrict__ outm)
{
    size_t g = (size_t)blockIdx.x * 256 + threadIdx.x;
    int k8 = (int)(g & 127);
    size_t t = g >> 7;
    int q = (int)(t & 1023);
    int b = (int)(t >> 10);
    size_t k = (size_t)k8 * 8;

    float acc8[8];
    #pragma unroll
    for (int j = 0; j < 8; j++) acc8[j] = 0.f;
    #pragma unroll
    for (int h = 0; h < HH; h++) {
        size_t off = ((size_t)(b * HH + h) * SS + q) * SS + k;
        uint4 v4 = *(const uint4*)&P[off];
        const uint32_t* p = (const uint32_t*)&v4;
        #pragma unroll
        for (int j = 0; j < 4; j++) {
            float2 hh = __half22float2(*(__half2*)&p[j]);
            acc8[2*j]   += hh.x;
            acc8[2*j+1] += hh.y;
        }
    }
    size_t ob = ((size_t)(b * SS + q)) * SS + k;
    const float inv = 1.0f / HH;
    float4 o0 = make_float4(acc8[0]*inv, acc8[1]*inv, acc8[2]*inv, acc8[3]*inv);
    float4 o1 = make_float4(acc8[4]*inv, acc8[5]*inv, acc8[6]*inv, acc8[7]*inv);
    *(float4*)&outm[ob]     = o0;
    *(float4*)&outm[ob + 4] = o1;
}

// ---------------------------------------------------------------------------
// Host launcher (fork-join: attn_mean overlaps PV + out-proj)
// ---------------------------------------------------------------------------
extern "C" void kernel_launch(void* const* d_in, const int* in_sizes, int n_in,
                              void* d_out, int out_size)
{
    const float* x     = (const float*)d_in[0];
    const float* w_in  = (const float*)d_in[1];
    const float* b_in  = (const float*)d_in[2];
    const float* w_out = (const float*)d_in[3];
    const float* b_out = (const float*)d_in[4];
    float* out = (float*)d_out;

    __half *xh, *xl, *wih, *wil, *woh, *wol;
    __half *q, *k, *v, *p, *ao;
    cudaGetSymbolAddress((void**)&xh,  g_xh);
    cudaGetSymbolAddress((void**)&xl,  g_xl);
    cudaGetSymbolAddress((void**)&wih, g_wih);
    cudaGetSymbolAddress((void**)&wil, g_wil);
    cudaGetSymbolAddress((void**)&woh, g_woh);
    cudaGetSymbolAddress((void**)&wol, g_wol);
    cudaGetSymbolAddress((void**)&q,   g_q);
    cudaGetSymbolAddress((void**)&k,   g_k);
    cudaGetSymbolAddress((void**)&v,   g_v);
    cudaGetSymbolAddress((void**)&p,   g_p);
    cudaGetSymbolAddress((void**)&ao,  g_ao);

    static cudaStream_t s1 = nullptr;
    static cudaEvent_t evA = nullptr, evB = nullptr;
    if (!s1) {
        cudaStreamCreateWithFlags(&s1, cudaStreamNonBlocking);
        cudaEventCreateWithFlags(&evA, cudaEventDisableTiming);
        cudaEventCreateWithFlags(&evB, cudaEventDisableTiming);
    }

    cudaFuncSetAttribute(mma_gemm_qkv,
                         cudaFuncAttributeMaxDynamicSharedMemorySize, GEMM_SMEM);
    cudaFuncSetAttribute(mma_gemm_out,
                         cudaFuncAttributeMaxDynamicSharedMemorySize, GEMM_SMEM);
    cudaFuncSetAttribute(attn_scores_mma,
                         cudaFuncAttributeMaxDynamicSharedMemorySize, SC_SMEM);
    cudaFuncSetAttribute(attn_pv_mma,
                         cudaFuncAttributeMaxDynamicSharedMemorySize, PV_SMEM);

    // 0. pre-split inputs (weights pre-scaled x64)
    split_kernel<<<(MROWS * DD / 4 + 255) / 256, 256>>>(x, xh, xl, 1.0f, MROWS * DD / 4);
    split_kernel<<<(DD * 3 * DD / 4 + 255) / 256, 256>>>(w_in, wih, wil, WSCALE, DD * 3 * DD / 4);
    split_kernel<<<(DD * DD / 4 + 255) / 256, 256>>>(w_out, woh, wol, WSCALE, DD * DD / 4);

    // 1. QKV GEMM -> fp16 q/k/v per head (q,k 1-pass; v 3-pass)
    mma_gemm_qkv<<<dim3(3 * DD / 128, MROWS / 128), 128, GEMM_SMEM>>>(
        xh, xl, wih, wil, b_in, q, k, v, MROWS, 3 * DD, DD);

    // 2. scores (1-pass) + softmax -> hi-only fp16 P
    attn_scores_mma<<<dim3(SS / 32, HH, BB), 256, SC_SMEM>>>(q, k, p);

    // fork: head-mean on side stream, overlapping PV + out-proj
    cudaEventRecord(evA, 0);
    cudaStreamWaitEvent(s1, evA, 0);
    attn_mean_kernel<<<(BB * SS * SS / 8) / 256, 256, 0, s1>>>(
        p, out + (size_t)BB * SS * SS);
    cudaEventRecord(evB, s1);

    // 3. P @ V (1-pass) -> hi-only fp16 AO (x16)
    attn_pv_mma<<<dim3(SS / 256, HH, BB), 256, PV_SMEM>>>(p, v, ao);

    // 5. output projection (2-pass: AOh*wh + AOh*wl)
    mma_gemm_out<<<dim3(DD / 128, MROWS / 128), 128, GEMM_SMEM>>>(
        ao, ao, woh, wol, b_out, out, MROWS, DD, DD);

    // join
    cudaStreamWaitEvent(0, evB, 0);
}

// round 14
// speedup vs baseline: 1.7495x; 1.2488x over previous
#include <cuda_runtime.h>
#include <cuda_fp16.h>
#include <cstdint>

// Problem constants
#define BB 4
#define SS 1024
#define DD 1024
#define HH 16
#define HD 64
#define MROWS (BB*SS)          // 4096
#define QSCALE 0.03125f        // 1024^-0.5 (exact power of 2)
#define WSCALE 64.0f           // weight pre-scale (keeps fp16 lo out of subnormals)
#define AOSCALE 16.0f          // AO pre-scale

// ---------------------------------------------------------------------------
// Scratch (fp16; x/P/AO hi-only, weights split)
// ---------------------------------------------------------------------------
__device__ __half g_xh[(size_t)MROWS * DD];
__device__ __half g_wih[(size_t)DD * 3 * DD], g_wil[(size_t)DD * 3 * DD];  // 64*w_in
__device__ __half g_woh[(size_t)DD * DD],     g_wol[(size_t)DD * DD];      // 64*w_out
__device__ __half g_q[(size_t)BB*HH*SS*HD];
__device__ __half g_k[(size_t)BB*HH*SS*HD];
__device__ __half g_v[(size_t)BB*HH*SS*HD];
__device__ __half g_p[(size_t)BB*HH*SS*SS];                                 // hi-only P
__device__ __half g_ao[(size_t)MROWS * DD];                                 // hi-only 16*AO

// ---------------------------------------------------------------------------
// MMA / ldmatrix / cp.async helpers (fp16)
// ---------------------------------------------------------------------------
__device__ __forceinline__ void mma16816(float* d, const uint32_t* a, const uint32_t* b) {
    asm volatile(
        "mma.sync.aligned.m16n8k16.row.col.f32.f16.f16.f32 "
        "{%0,%1,%2,%3}, {%4,%5,%6,%7}, {%8,%9}, {%0,%1,%2,%3};"
        : "+f"(d[0]), "+f"(d[1]), "+f"(d[2]), "+f"(d[3])
        : "r"(a[0]), "r"(a[1]), "r"(a[2]), "r"(a[3]), "r"(b[0]), "r"(b[1]));
}
__device__ __forceinline__ void ldsm_x4(uint32_t* r, uint32_t addr) {
    asm volatile("ldmatrix.sync.aligned.m8n8.x4.shared.b16 {%0,%1,%2,%3}, [%4];"
                 : "=r"(r[0]), "=r"(r[1]), "=r"(r[2]), "=r"(r[3]) : "r"(addr));
}
__device__ __forceinline__ void ldsm_x2t(uint32_t* r, uint32_t addr) {
    asm volatile("ldmatrix.sync.aligned.m8n8.x2.trans.shared.b16 {%0,%1}, [%2];"
                 : "=r"(r[0]), "=r"(r[1]) : "r"(addr));
}
__device__ __forceinline__ void split_fp16(float v, __half& h, __half& l) {
    h = __float2half_rn(v);
    l = __float2half_rn(v - __half2float(h));
}
__device__ __forceinline__ void cpa16(uint32_t s, const void* g) {
    asm volatile("cp.async.cg.shared.global [%0], [%1], 16;" :: "r"(s), "l"(g));
}
__device__ __forceinline__ void cp_commit() { asm volatile("cp.async.commit_group;"); }
template<int N> __device__ __forceinline__ void cp_wait() {
    asm volatile("cp.async.wait_group %0;" :: "n"(N));
}

// ---------------------------------------------------------------------------
// split kernels
// ---------------------------------------------------------------------------
__global__ __launch_bounds__(256) void split_kernel(
    const float* __restrict__ in, __half* __restrict__ hi,
    __half* __restrict__ lo, float scale, int n4)
{
    int i = blockIdx.x * 256 + threadIdx.x;
    if (i >= n4) return;
    float4 v = ((const float4*)in)[i];
    __half h0, l0, h1, l1, h2, l2, h3, l3;
    split_fp16(v.x * scale, h0, l0); split_fp16(v.y * scale, h1, l1);
    split_fp16(v.z * scale, h2, l2); split_fp16(v.w * scale, h3, l3);
    ((__half2*)hi)[2 * i]     = __halves2half2(h0, h1);
    ((__half2*)hi)[2 * i + 1] = __halves2half2(h2, h3);
    ((__half2*)lo)[2 * i]     = __halves2half2(l0, l1);
    ((__half2*)lo)[2 * i + 1] = __halves2half2(l2, l3);
}

// hi-only convert (for x)
__global__ __launch_bounds__(256) void cvt_kernel(
    const float* __restrict__ in, __half* __restrict__ hi, int n4)
{
    int i = blockIdx.x * 256 + threadIdx.x;
    if (i >= n4) return;
    float4 v = ((const float4*)in)[i];
    ((__half2*)hi)[2 * i]     = __halves2half2(__float2half_rn(v.x), __float2half_rn(v.y));
    ((__half2*)hi)[2 * i + 1] = __halves2half2(__float2half_rn(v.z), __float2half_rn(v.w));
}

// ---------------------------------------------------------------------------
// GEMM tile (BM=BN=128, BK=32): 4 warps, warp tile 64x64.
// 3-stage cp.async pipeline. useBl: add ah*bl second pass.
// ---------------------------------------------------------------------------
#define ASTR 40
#define BSTR 136
#define AH_OFF 0
#define BH_OFF 10240
#define BL_OFF 18944
#define STAGE_B 27648
#define GEMM_SMEM (STAGE_B * 3)

#define GEMM_PROLOG(useBlExpr) \
    extern __shared__ char dynsm[]; \
    uint32_t smbase = (uint32_t)__cvta_generic_to_shared(dynsm); \
    int bx = blockIdx.x, by = blockIdx.y; \
    int tid = threadIdx.x, lane = tid & 31, wid = tid >> 5; \
    int wm = (wid & 1) * 64, wn = (wid >> 1) * 64; \
    const bool useBl = (useBlExpr); \
    uint32_t a_off = (uint32_t)((wm + (lane & 15)) * ASTR + (lane >> 4) * 8) * 2; \
    uint32_t b_off = (uint32_t)((lane & 15) * BSTR + wn) * 2; \
    float acc[4][8][4]; \
    _Pragma("unroll") for (int i = 0; i < 4; i++) \
        _Pragma("unroll") for (int j = 0; j < 8; j++) \
            _Pragma("unroll") for (int c = 0; c < 4; c++) acc[i][j][c] = 0.f; \
    const int nk = K >> 5; \
    auto load_stage = [&](int st, int kt) { \
        uint32_t sb = smbase + st * STAGE_B; \
        _Pragma("unroll") for (int i = 0; i < 4; i++) { \
            int row = (tid >> 2) + i * 32; \
            size_t g = (size_t)(by * 128 + row) * K + kt + (tid & 3) * 8; \
            cpa16(sb + AH_OFF + (uint32_t)(row * ASTR + (tid & 3) * 8) * 2, Ahg + g); \
        } \
        _Pragma("unroll") for (int i = 0; i < 4; i++) { \
            int row = (tid >> 4) + i * 8; \
            size_t g = (size_t)(kt + row) * N + bx * 128 + (tid & 15) * 8; \
            cpa16(sb + BH_OFF + (uint32_t)(row * BSTR + (tid & 15) * 8) * 2, Bhg + g); \
            if (useBl) cpa16(sb + BL_OFF + (uint32_t)(row * BSTR + (tid & 15) * 8) * 2, Blg + g); \
        } \
        cp_commit(); \
    }; \
    load_stage(0, 0); \
    load_stage(1, 32); \
    for (int i = 0; i < nk; i++) { \
        if (i + 1 < nk) cp_wait<1>(); else cp_wait<0>(); \
        __syncthreads(); \
        if (i + 2 < nk) load_stage((i + 2) % 3, (i + 2) * 32); \
        uint32_t sb = smbase + (i % 3) * STAGE_B; \
        _Pragma("unroll") for (int ks = 0; ks < 2; ks++) { \
            uint32_t ahf[4][4]; \
            _Pragma("unroll") for (int mi = 0; mi < 4; mi++) { \
                uint32_t off = a_off + (uint32_t)(mi * 16 * ASTR + ks * 16) * 2; \
                ldsm_x4(ahf[mi], sb + AH_OFF + off); \
            } \
            _Pragma("unroll") for (int nb = 0; nb < 2; nb++) { \
                uint32_t bhf[4][2]; \
                _Pragma("unroll") for (int nj = 0; nj < 4; nj++) { \
                    uint32_t off = b_off + (uint32_t)(ks * 16 * BSTR + (nb * 4 + nj) * 8) * 2; \
                    ldsm_x2t(bhf[nj], sb + BH_OFF + off); \
                } \
                _Pragma("unroll") for (int nj = 0; nj < 4; nj++) \
                    _Pragma("unroll") for (int mi = 0; mi < 4; mi++) \
                        mma16816(acc[mi][nb * 4 + nj], ahf[mi], bhf[nj]); \
                if (useBl) { \
                    uint32_t blf[4][2]; \
                    _Pragma("unroll") for (int nj = 0; nj < 4; nj++) { \
                        uint32_t off = b_off + (uint32_t)(ks * 16 * BSTR + (nb * 4 + nj) * 8) * 2; \
                        ldsm_x2t(blf[nj], sb + BL_OFF + off); \
                    } \
                    _Pragma("unroll") for (int nj = 0; nj < 4; nj++) \
                        _Pragma("unroll") for (int mi = 0; mi < 4; mi++) \
                            mma16816(acc[mi][nb * 4 + nj], ahf[mi], blf[nj]); \
                } \
            } \
        } \
    } \
    __syncthreads();

// ---------------------------------------------------------------------------
// QKV GEMM: uniform 1-pass (xh * wh). Stores hi-only fp16 [b,h,s,d].
// ---------------------------------------------------------------------------
__global__ __launch_bounds__(128, 2) void mma_gemm_qkv(
    const __half* __restrict__ Ahg,
    const __half* __restrict__ Bhg, const __half* __restrict__ Blg,
    const float* __restrict__ bias,
    __half* __restrict__ q, __half* __restrict__ k, __half* __restrict__ v,
    int M, int N, int K)
{
    GEMM_PROLOG(false)

    int part = (bx * 128) >> 10;
    __half* dst = part == 0 ? q : (part == 1 ? k : v);
    int head = ((bx * 128 + wn) & 1023) >> 6;
    int bq = (by * 128) >> 10;
    int group = lane >> 2, tig = lane & 3;
    const float inv = 1.0f / WSCALE;
    #pragma unroll
    for (int mi = 0; mi < 4; mi++) {
        int s0 = ((by * 128) & 1023) + wm + mi * 16 + group;
        #pragma unroll
        for (int ni = 0; ni < 8; ni++) {
            int col = bx * 128 + wn + ni * 8 + tig * 2;
            int d = ni * 8 + tig * 2;
            float b0 = bias[col], b1 = bias[col + 1];
            float v00 = acc[mi][ni][0] * inv + b0, v01 = acc[mi][ni][1] * inv + b1;
            float v10 = acc[mi][ni][2] * inv + b0, v11 = acc[mi][ni][3] * inv + b1;
            size_t o0 = ((size_t)(bq * HH + head) * SS + s0) * HD + d;
            size_t o1 = o0 + 8 * HD;
            *(__half2*)&dst[o0] = __halves2half2(__float2half_rn(v00), __float2half_rn(v01));
            *(__half2*)&dst[o1] = __halves2half2(__float2half_rn(v10), __float2half_rn(v11));
        }
    }
}

// ---------------------------------------------------------------------------
// Out-projection GEMM: 2-pass (ah*bh + ah*bl); val = acc/(WSCALE*AOSCALE)+bias
// ---------------------------------------------------------------------------
__global__ __launch_bounds__(128, 2) void mma_gemm_out(
    const __half* __restrict__ Ahg,
    const __half* __restrict__ Bhg, const __half* __restrict__ Blg,
    const float* __restrict__ bias, float* __restrict__ C,
    int M, int N, int K)
{
    GEMM_PROLOG(true)

    int group = lane >> 2, tig = lane & 3;
    const float inv = 1.0f / (WSCALE * AOSCALE);
    #pragma unroll
    for (int mi = 0; mi < 4; mi++) {
        int row0 = by * 128 + wm + mi * 16 + group;
        #pragma unroll
        for (int ni = 0; ni < 8; ni++) {
            int col = bx * 128 + wn + ni * 8 + tig * 2;
            float b0 = bias[col], b1 = bias[col + 1];
            *(float2*)&C[(size_t)row0 * N + col] =
                make_float2(acc[mi][ni][0] * inv + b0, acc[mi][ni][1] * inv + b1);
            *(float2*)&C[(size_t)(row0 + 8) * N + col] =
                make_float2(acc[mi][ni][2] * inv + b0, acc[mi][ni][3] * inv + b1);
        }
    }
}

// ---------------------------------------------------------------------------
// Scores + softmax: per (b,h,32q). 1-pass fp16: S = QSCALE * (q @ k^T).
// ---------------------------------------------------------------------------
#define SC_Q   132096
#define SC_K   136704
#define SC_KSTAGE 36864
#define SC_SMEM 210432

__global__ __launch_bounds__(256) void attn_scores_mma(
    const __half* __restrict__ q, const __half* __restrict__ k,
    __half* __restrict__ P)
{
    extern __shared__ char dynsm[];
    float* Ssc = (float*)dynsm;
    uint32_t smbase = (uint32_t)__cvta_generic_to_shared(dynsm);

    int b = blockIdx.z, h = blockIdx.y, q0 = blockIdx.x * 32;
    int tid = threadIdx.x, lane = tid & 31, wid = tid >> 5;
    int wm = (wid & 1) * 16;
    int wn = (wid >> 1) * 64;

    {
        size_t qb = ((size_t)(b * HH + h) * SS + q0) * HD;
        int row = tid >> 3, c8 = (tid & 7) * 8;
        *(uint4*)(dynsm + SC_Q + (row * 72 + c8) * 2) = *(const uint4*)&q[qb + row * 64 + c8];
    }

    auto load_k = [&](int st, int kt) {
        uint32_t kb = smbase + SC_K + st * SC_KSTAGE;
        size_t gb = ((size_t)(b * HH + h) * SS + kt) * HD;
        #pragma unroll
        for (int it = 0; it < 8; it++) {
            int idx = tid + it * 256;
            int row = idx >> 3, c8 = (idx & 7) * 8;
            cpa16(kb + (uint32_t)(row * 72 + c8) * 2, k + gb + (size_t)row * 64 + c8);
        }
        cp_commit();
    };
    load_k(0, 0);
    load_k(1, 256);

    uint32_t aq_off = (uint32_t)((wm + (lane & 15)) * 72 + (lane >> 4) * 8) * 2;
    int rr_ = lane & 7, halfk = (lane >> 3) & 1, q2 = lane >> 4;

    for (int i = 0; i < 4; i++) {
        if (i < 3) cp_wait<1>(); else cp_wait<0>();
        __syncthreads();
        uint32_t kb = smbase + SC_K + (i & 1) * SC_KSTAGE;

        float acc[8][4];
        #pragma unroll
        for (int a = 0; a < 8; a++)
            #pragma unroll
            for (int c = 0; c < 4; c++) acc[a][c] = 0.f;

        #pragma unroll
        for (int ks = 0; ks < 4; ks++) {
            uint32_t ahf[4];
            ldsm_x4(ahf, smbase + SC_Q + aq_off + ks * 32);
            uint32_t bhf[4][4];
            #pragma unroll
            for (int nb = 0; nb < 4; nb++) {
                uint32_t boff = (uint32_t)((wn + nb * 16 + q2 * 8 + rr_) * 72 + halfk * 8 + ks * 16) * 2;
                ldsm_x4(bhf[nb], kb + boff);
            }
            #pragma unroll
            for (int nb = 0; nb < 4; nb++) {
                mma16816(acc[nb*2],   ahf, bhf[nb]);
                mma16816(acc[nb*2+1], ahf, bhf[nb] + 2);
            }
        }

        int kt = i * 256;
        int group = lane >> 2, tig = lane & 3;
        #pragma unroll
        for (int ni = 0; ni < 8; ni++) {
            int row = wm + group;
            int col = kt + wn + ni * 8 + tig * 2;
            *(float2*)&Ssc[row * 1032 + col] =
                make_float2(acc[ni][0] * QSCALE, acc[ni][1] * QSCALE);
            *(float2*)&Ssc[(row + 8) * 1032 + col] =
                make_float2(acc[ni][2] * QSCALE, acc[ni][3] * QSCALE);
        }
        __syncthreads();
        if (i + 2 < 4) load_k((i + 2) & 1, (i + 2) * 256);
    }

    for (int rr = 0; rr < 4; rr++) {
        int row = wid * 4 + rr;
        float2 v2[16];
        float m = -1e30f;
        #pragma unroll
        for (int i2 = 0; i2 < 16; i2++) {
            v2[i2] = *(float2*)&Ssc[row * 1032 + (lane + i2 * 32) * 2];
            m = fmaxf(m, fmaxf(v2[i2].x, v2[i2].y));
        }
        #pragma unroll
        for (int o = 16; o; o >>= 1) m = fmaxf(m, __shfl_xor_sync(0xffffffffu, m, o));
        float s = 0.f;
        #pragma unroll
        for (int i2 = 0; i2 < 16; i2++) {
            v2[i2].x = __expf(v2[i2].x - m);
            v2[i2].y = __expf(v2[i2].y - m);
            s += v2[i2].x + v2[i2].y;
        }
        #pragma unroll
        for (int o = 16; o; o >>= 1) s += __shfl_xor_sync(0xffffffffu, s, o);
        float inv = 1.f / s;
        size_t gb = ((size_t)(b * HH + h) * SS + q0 + row) * SS;
        #pragma unroll
        for (int i2 = 0; i2 < 16; i2++) {
            size_t o = gb + (size_t)(lane + i2 * 32) * 2;
            *(__half2*)&P[o] = __halves2half2(
                __float2half_rn(v2[i2].x * inv), __float2half_rn(v2[i2].y * inv));
        }
    }
}

// ---------------------------------------------------------------------------
// PV: AO = P @ V per (b,h,256q). 1-pass fp16. AO stored x16 hi-only.
// ---------------------------------------------------------------------------
#define PV_P  0
#define PV_VH 36864
#define PV_STAGE 46080
#define PV_SMEM 92160

__global__ __launch_bounds__(256) void attn_pv_mma(
    const __half* __restrict__ P, const __half* __restrict__ v,
    __half* __restrict__ AO)
{
    extern __shared__ char dynsm[];
    uint32_t smbase = (uint32_t)__cvta_generic_to_shared(dynsm);

    int b = blockIdx.z, h = blockIdx.y, q0 = blockIdx.x * 256;
    int tid = threadIdx.x, lane = tid & 31, wid = tid >> 5;

    auto load_stage = [&](int st, int kt) {
        uint32_t sb = smbase + st * PV_STAGE;
        size_t pb = ((size_t)(b * HH + h) * SS + q0) * SS + kt;
        #pragma unroll
        for (int it = 0; it < 8; it++) {
            int idx = tid + it * 256;
            int row = idx >> 3, c8 = (idx & 7) * 8;
            cpa16(sb + PV_P + (uint32_t)(row * 72 + c8) * 2, P + pb + (size_t)row * SS + c8);
        }
        size_t vb = ((size_t)(b * HH + h) * SS + kt) * HD;
        #pragma unroll
        for (int it = 0; it < 2; it++) {
            int idx = tid + it * 256;
            int row = idx >> 3, c8 = (idx & 7) * 8;
            cpa16(sb + PV_VH + (uint32_t)(row * 72 + c8) * 2, v + vb + row * 64 + c8);
        }
        cp_commit();
    };

    float acc[2][8][4];
    #pragma unroll
    for (int a = 0; a < 2; a++)
        #pragma unroll
        for (int j = 0; j < 8; j++)
            #pragma unroll
            for (int c = 0; c < 4; c++) acc[a][j][c] = 0.f;

    uint32_t ap_off = (uint32_t)((wid * 32 + (lane & 15)) * 72 + (lane >> 4) * 8) * 2;
    uint32_t bv_off = (uint32_t)((lane & 15) * 72) * 2;

    load_stage(0, 0);
    load_stage(1, 64);

    for (int i = 0; i < 16; i++) {
        if (i < 15) cp_wait<1>(); else cp_wait<0>();
        __syncthreads();
        uint32_t sb = smbase + (i & 1) * PV_STAGE;
        #pragma unroll
        for (int ks = 0; ks < 4; ks++) {
            uint32_t ahf[2][4];
            #pragma unroll
            for (int mi = 0; mi < 2; mi++) {
                uint32_t off = ap_off + (uint32_t)(mi * 16 * 72 + ks * 16) * 2;
                ldsm_x4(ahf[mi], sb + PV_P + off);
            }
            #pragma unroll
            for (int nb = 0; nb < 2; nb++) {
                uint32_t bhf[4][2];
                #pragma unroll
                for (int nj = 0; nj < 4; nj++) {
                    uint32_t off = bv_off + (uint32_t)(ks * 16 * 72 + (nb * 4 + nj) * 8) * 2;
                    ldsm_x2t(bhf[nj], sb + PV_VH + off);
                }
                #pragma unroll
                for (int nj = 0; nj < 4; nj++)
                    #pragma unroll
                    for (int mi = 0; mi < 2; mi++)
                        mma16816(acc[mi][nb*4+nj], ahf[mi], bhf[nj]);
            }
        }
        __syncthreads();
        if (i + 2 < 16) load_stage((i + 2) & 1, (i + 2) * 64);
    }

    int group = lane >> 2, tig = lane & 3;
    #pragma unroll
    for (int mi = 0; mi < 2; mi++) {
        #pragma unroll
        for (int ni = 0; ni < 8; ni++) {
            int d = ni * 8 + tig * 2;
            int r0 = q0 + wid * 32 + mi * 16 + group;
            size_t o0 = (size_t)(b * SS + r0) * DD + h * HD + d;
            size_t o1 = o0 + (size_t)8 * DD;
            *(__half2*)&AO[o0] = __halves2half2(
                __float2half_rn(acc[mi][ni][0] * AOSCALE),
                __float2half_rn(acc[mi][ni][1] * AOSCALE));
            *(__half2*)&AO[o1] = __halves2half2(
                __float2half_rn(acc[mi][ni][2] * AOSCALE),
                __float2half_rn(acc[mi][ni][3] * AOSCALE));
        }
    }
}

// ---------------------------------------------------------------------------
// attn_mean[b,q,k] = (1/H) * sum_h P
// ---------------------------------------------------------------------------
__global__ __launch_bounds__(256) void attn_mean_kernel(
    const __half* __restrict__ P, float* __restrict__ outm)
{
    size_t g = (size_t)blockIdx.x * 256 + threadIdx.x;
    int k8 = (int)(g & 127);
    size_t t = g >> 7;
    int q = (int)(t & 1023);
    int b = (int)(t >> 10);
    size_t k = (size_t)k8 * 8;

    float acc8[8];
    #pragma unroll
    for (int j = 0; j < 8; j++) acc8[j] = 0.f;
    #pragma unroll
    for (int h = 0; h < HH; h++) {
        size_t off = ((size_t)(b * HH + h) * SS + q) * SS + k;
        uint4 v4 = *(const uint4*)&P[off];
        const uint32_t* p = (const uint32_t*)&v4;
        #pragma unroll
        for (int j = 0; j < 4; j++) {
            float2 hh = __half22float2(*(__half2*)&p[j]);
            acc8[2*j]   += hh.x;
            acc8[2*j+1] += hh.y;
        }
    }
    size_t ob = ((size_t)(b * SS + q)) * SS + k;
    const float inv = 1.0f / HH;
    float4 o0 = make_float4(acc8[0]*inv, acc8[1]*inv, acc8[2]*inv, acc8[3]*inv);
    float4 o1 = make_float4(acc8[4]*inv, acc8[5]*inv, acc8[6]*inv, acc8[7]*inv);
    *(float4*)&outm[ob]     = o0;
    *(float4*)&outm[ob + 4] = o1;
}

// ---------------------------------------------------------------------------
// Host launcher. Side stream forked LEGALLY: s1's first op is a
// cudaStreamWaitEvent on an event recorded in the capture-origin stream.
// ---------------------------------------------------------------------------
extern "C" void kernel_launch(void* const* d_in, const int* in_sizes, int n_in,
                              void* d_out, int out_size)
{
    const float* x     = (const float*)d_in[0];
    const float* w_in  = (const float*)d_in[1];
    const float* b_in  = (const float*)d_in[2];
    const float* w_out = (const float*)d_in[3];
    const float* b_out = (const float*)d_in[4];
    float* out = (float*)d_out;

    __half *xh, *wih, *wil, *woh, *wol;
    __half *q, *k, *v, *p, *ao;
    cudaGetSymbolAddress((void**)&xh,  g_xh);
    cudaGetSymbolAddress((void**)&wih, g_wih);
    cudaGetSymbolAddress((void**)&wil, g_wil);
    cudaGetSymbolAddress((void**)&woh, g_woh);
    cudaGetSymbolAddress((void**)&wol, g_wol);
    cudaGetSymbolAddress((void**)&q,   g_q);
    cudaGetSymbolAddress((void**)&k,   g_k);
    cudaGetSymbolAddress((void**)&v,   g_v);
    cudaGetSymbolAddress((void**)&p,   g_p);
    cudaGetSymbolAddress((void**)&ao,  g_ao);

    static cudaStream_t s1 = nullptr;
    static cudaEvent_t ev0 = nullptr, evA = nullptr, evB = nullptr, evC = nullptr;
    if (!s1) {
        cudaStreamCreateWithFlags(&s1, cudaStreamNonBlocking);
        cudaEventCreateWithFlags(&ev0, cudaEventDisableTiming);
        cudaEventCreateWithFlags(&evA, cudaEventDisableTiming);
        cudaEventCreateWithFlags(&evB, cudaEventDisableTiming);
        cudaEventCreateWithFlags(&evC, cudaEventDisableTiming);
    }

    cudaFuncSetAttribute(mma_gemm_qkv,
                         cudaFuncAttributeMaxDynamicSharedMemorySize, GEMM_SMEM);
    cudaFuncSetAttribute(mma_gemm_out,
                         cudaFuncAttributeMaxDynamicSharedMemorySize, GEMM_SMEM);
    cudaFuncSetAttribute(attn_scores_mma,
                         cudaFuncAttributeMaxDynamicSharedMemorySize, SC_SMEM);
    cudaFuncSetAttribute(attn_pv_mma,
                         cudaFuncAttributeMaxDynamicSharedMemorySize, PV_SMEM);

    // Legal fork: record on origin stream FIRST, then s1 waits on it.
    cudaEventRecord(ev0, 0);
    cudaStreamWaitEvent(s1, ev0, 0);

    // 0. convert x (hi-only) + split w_in on main; w_out split on side stream
    cvt_kernel<<<(MROWS * DD / 4 + 255) / 256, 256>>>(x, xh, MROWS * DD / 4);
    split_kernel<<<(DD * 3 * DD / 4 + 255) / 256, 256>>>(w_in, wih, wil, WSCALE, DD * 3 * DD / 4);
    split_kernel<<<(DD * DD / 4 + 255) / 256, 256, 0, s1>>>(w_out, woh, wol, WSCALE, DD * DD / 4);
    cudaEventRecord(evC, s1);

    // 1. QKV GEMM (uniform 1-pass) -> fp16 q/k/v per head
    mma_gemm_qkv<<<dim3(3 * DD / 128, MROWS / 128), 128, GEMM_SMEM>>>(
        xh, wih, wil, b_in, q, k, v, MROWS, 3 * DD, DD);

    // 2. scores (1-pass) + softmax -> hi-only fp16 P
    attn_scores_mma<<<dim3(SS / 32, HH, BB), 256, SC_SMEM>>>(q, k, p);

    // fork: head-mean on side stream, overlapping PV + out-proj
    cudaEventRecord(evA, 0);
    cudaStreamWaitEvent(s1, evA, 0);
    attn_mean_kernel<<<(BB * SS * SS / 8) / 256, 256, 0, s1>>>(
        p, out + (size_t)BB * SS * SS);
    cudaEventRecord(evB, s1);

    // 3. P @ V (1-pass) -> hi-only fp16 AO (x16)
    attn_pv_mma<<<dim3(SS / 256, HH, BB), 256, PV_SMEM>>>(p, v, ao);

    // 5. output projection (2-pass), gated on w_out split
    cudaStreamWaitEvent(0, evC, 0);
    mma_gemm_out<<<dim3(DD / 128, MROWS / 128), 128, GEMM_SMEM>>>(
        ao, woh, wol, b_out, out, MROWS, DD, DD);

    // join
    cudaStreamWaitEvent(0, evB, 0);
}

// round 15
// speedup vs baseline: 1.8614x; 1.0640x over previous
#include <cuda_runtime.h>
#include <cuda_fp16.h>
#include <cstdint>

// Problem constants
#define BB 4
#define SS 1024
#define DD 1024
#define HH 16
#define HD 64
#define MROWS (BB*SS)          // 4096
#define QSCALE 0.03125f        // 1024^-0.5 (exact power of 2)

// ---------------------------------------------------------------------------
// Scratch (all fp16 hi-only)
// ---------------------------------------------------------------------------
__device__ __half g_xh[(size_t)MROWS * DD];
__device__ __half g_wih[(size_t)DD * 3 * DD];
__device__ __half g_woh[(size_t)DD * DD];
__device__ __half g_q[(size_t)BB*HH*SS*HD];
__device__ __half g_k[(size_t)BB*HH*SS*HD];
__device__ __half g_v[(size_t)BB*HH*SS*HD];
__device__ __half g_p[(size_t)BB*HH*SS*SS];
__device__ __half g_ao[(size_t)MROWS * DD];

// ---------------------------------------------------------------------------
// MMA / ldmatrix / cp.async helpers (fp16)
// ---------------------------------------------------------------------------
__device__ __forceinline__ void mma16816(float* d, const uint32_t* a, const uint32_t* b) {
    asm volatile(
        "mma.sync.aligned.m16n8k16.row.col.f32.f16.f16.f32 "
        "{%0,%1,%2,%3}, {%4,%5,%6,%7}, {%8,%9}, {%0,%1,%2,%3};"
        : "+f"(d[0]), "+f"(d[1]), "+f"(d[2]), "+f"(d[3])
        : "r"(a[0]), "r"(a[1]), "r"(a[2]), "r"(a[3]), "r"(b[0]), "r"(b[1]));
}
__device__ __forceinline__ void ldsm_x4(uint32_t* r, uint32_t addr) {
    asm volatile("ldmatrix.sync.aligned.m8n8.x4.shared.b16 {%0,%1,%2,%3}, [%4];"
                 : "=r"(r[0]), "=r"(r[1]), "=r"(r[2]), "=r"(r[3]) : "r"(addr));
}
__device__ __forceinline__ void ldsm_x2t(uint32_t* r, uint32_t addr) {
    asm volatile("ldmatrix.sync.aligned.m8n8.x2.trans.shared.b16 {%0,%1}, [%2];"
                 : "=r"(r[0]), "=r"(r[1]) : "r"(addr));
}
__device__ __forceinline__ void cpa16(uint32_t s, const void* g) {
    asm volatile("cp.async.cg.shared.global [%0], [%1], 16;" :: "r"(s), "l"(g));
}
__device__ __forceinline__ void cp_commit() { asm volatile("cp.async.commit_group;"); }
template<int N> __device__ __forceinline__ void cp_wait() {
    asm volatile("cp.async.wait_group %0;" :: "n"(N));
}

// ---------------------------------------------------------------------------
// hi-only convert: fp32 -> fp16
// ---------------------------------------------------------------------------
__global__ __launch_bounds__(256) void cvt_kernel(
    const float* __restrict__ in, __half* __restrict__ hi, int n4)
{
    int i = blockIdx.x * 256 + threadIdx.x;
    if (i >= n4) return;
    float4 v = ((const float4*)in)[i];
    ((__half2*)hi)[2 * i]     = __halves2half2(__float2half_rn(v.x), __float2half_rn(v.y));
    ((__half2*)hi)[2 * i + 1] = __halves2half2(__float2half_rn(v.z), __float2half_rn(v.w));
}

// ---------------------------------------------------------------------------
// GEMM tile (BM=BN=128, BK=32): 4 warps, warp tile 64x64. 1-pass fp16.
// 3-stage cp.async pipeline, one barrier per iter.
// ---------------------------------------------------------------------------
#define ASTR 40
#define BSTR 136
#define AH_OFF 0
#define BH_OFF 10240
#define STAGE_B 18944
#define GEMM_SMEM (STAGE_B * 3)

#define GEMM_PROLOG \
    extern __shared__ char dynsm[]; \
    uint32_t smbase = (uint32_t)__cvta_generic_to_shared(dynsm); \
    int bx = blockIdx.x, by = blockIdx.y; \
    int tid = threadIdx.x, lane = tid & 31, wid = tid >> 5; \
    int wm = (wid & 1) * 64, wn = (wid >> 1) * 64; \
    uint32_t a_off = (uint32_t)((wm + (lane & 15)) * ASTR + (lane >> 4) * 8) * 2; \
    uint32_t b_off = (uint32_t)((lane & 15) * BSTR + wn) * 2; \
    float acc[4][8][4]; \
    _Pragma("unroll") for (int i = 0; i < 4; i++) \
        _Pragma("unroll") for (int j = 0; j < 8; j++) \
            _Pragma("unroll") for (int c = 0; c < 4; c++) acc[i][j][c] = 0.f; \
    const int nk = K >> 5; \
    auto load_stage = [&](int st, int kt) { \
        uint32_t sb = smbase + st * STAGE_B; \
        _Pragma("unroll") for (int i = 0; i < 4; i++) { \
            int row = (tid >> 2) + i * 32; \
            size_t g = (size_t)(by * 128 + row) * K + kt + (tid & 3) * 8; \
            cpa16(sb + AH_OFF + (uint32_t)(row * ASTR + (tid & 3) * 8) * 2, Ahg + g); \
        } \
        _Pragma("unroll") for (int i = 0; i < 4; i++) { \
            int row = (tid >> 4) + i * 8; \
            size_t g = (size_t)(kt + row) * N + bx * 128 + (tid & 15) * 8; \
            cpa16(sb + BH_OFF + (uint32_t)(row * BSTR + (tid & 15) * 8) * 2, Bhg + g); \
        } \
        cp_commit(); \
    }; \
    load_stage(0, 0); \
    load_stage(1, 32); \
    for (int i = 0; i < nk; i++) { \
        if (i + 1 < nk) cp_wait<1>(); else cp_wait<0>(); \
        __syncthreads(); \
        if (i + 2 < nk) load_stage((i + 2) % 3, (i + 2) * 32); \
        uint32_t sb = smbase + (i % 3) * STAGE_B; \
        _Pragma("unroll") for (int ks = 0; ks < 2; ks++) { \
            uint32_t ahf[4][4]; \
            _Pragma("unroll") for (int mi = 0; mi < 4; mi++) { \
                uint32_t off = a_off + (uint32_t)(mi * 16 * ASTR + ks * 16) * 2; \
                ldsm_x4(ahf[mi], sb + AH_OFF + off); \
            } \
            _Pragma("unroll") for (int nb = 0; nb < 2; nb++) { \
                uint32_t bhf[4][2]; \
                _Pragma("unroll") for (int nj = 0; nj < 4; nj++) { \
                    uint32_t off = b_off + (uint32_t)(ks * 16 * BSTR + (nb * 4 + nj) * 8) * 2; \
                    ldsm_x2t(bhf[nj], sb + BH_OFF + off); \
                } \
                _Pragma("unroll") for (int nj = 0; nj < 4; nj++) \
                    _Pragma("unroll") for (int mi = 0; mi < 4; mi++) \
                        mma16816(acc[mi][nb * 4 + nj], ahf[mi], bhf[nj]); \
            } \
        } \
    } \
    __syncthreads();

// ---------------------------------------------------------------------------
// QKV GEMM (1-pass): stores hi-only fp16 [b,h,s,d]
// ---------------------------------------------------------------------------
__global__ __launch_bounds__(128, 2) void mma_gemm_qkv(
    const __half* __restrict__ Ahg, const __half* __restrict__ Bhg,
    const float* __restrict__ bias,
    __half* __restrict__ q, __half* __restrict__ k, __half* __restrict__ v,
    int M, int N, int K)
{
    GEMM_PROLOG

    int part = (bx * 128) >> 10;
    __half* dst = part == 0 ? q : (part == 1 ? k : v);
    int head = ((bx * 128 + wn) & 1023) >> 6;
    int bq = (by * 128) >> 10;
    int group = lane >> 2, tig = lane & 3;
    #pragma unroll
    for (int mi = 0; mi < 4; mi++) {
        int s0 = ((by * 128) & 1023) + wm + mi * 16 + group;
        #pragma unroll
        for (int ni = 0; ni < 8; ni++) {
            int col = bx * 128 + wn + ni * 8 + tig * 2;
            int d = ni * 8 + tig * 2;
            float b0 = bias[col], b1 = bias[col + 1];
            float v00 = acc[mi][ni][0] + b0, v01 = acc[mi][ni][1] + b1;
            float v10 = acc[mi][ni][2] + b0, v11 = acc[mi][ni][3] + b1;
            size_t o0 = ((size_t)(bq * HH + head) * SS + s0) * HD + d;
            size_t o1 = o0 + 8 * HD;
            *(__half2*)&dst[o0] = __halves2half2(__float2half_rn(v00), __float2half_rn(v01));
            *(__half2*)&dst[o1] = __halves2half2(__float2half_rn(v10), __float2half_rn(v11));
        }
    }
}

// ---------------------------------------------------------------------------
// Out-projection GEMM (1-pass): fp32 out + bias
// ---------------------------------------------------------------------------
__global__ __launch_bounds__(128, 2) void mma_gemm_out(
    const __half* __restrict__ Ahg, const __half* __restrict__ Bhg,
    const float* __restrict__ bias, float* __restrict__ C,
    int M, int N, int K)
{
    GEMM_PROLOG

    int group = lane >> 2, tig = lane & 3;
    #pragma unroll
    for (int mi = 0; mi < 4; mi++) {
        int row0 = by * 128 + wm + mi * 16 + group;
        #pragma unroll
        for (int ni = 0; ni < 8; ni++) {
            int col = bx * 128 + wn + ni * 8 + tig * 2;
            float b0 = bias[col], b1 = bias[col + 1];
            *(float2*)&C[(size_t)row0 * N + col] =
                make_float2(acc[mi][ni][0] + b0, acc[mi][ni][1] + b1);
            *(float2*)&C[(size_t)(row0 + 8) * N + col] =
                make_float2(acc[mi][ni][2] + b0, acc[mi][ni][3] + b1);
        }
    }
}

// ---------------------------------------------------------------------------
// Scores + softmax: per (b,h,32q). 1-pass fp16: S = QSCALE * (q @ k^T).
// ---------------------------------------------------------------------------
#define SC_Q   132096
#define SC_K   136704
#define SC_KSTAGE 36864
#define SC_SMEM 210432

__global__ __launch_bounds__(256) void attn_scores_mma(
    const __half* __restrict__ q, const __half* __restrict__ k,
    __half* __restrict__ P)
{
    extern __shared__ char dynsm[];
    float* Ssc = (float*)dynsm;
    uint32_t smbase = (uint32_t)__cvta_generic_to_shared(dynsm);

    int b = blockIdx.z, h = blockIdx.y, q0 = blockIdx.x * 32;
    int tid = threadIdx.x, lane = tid & 31, wid = tid >> 5;
    int wm = (wid & 1) * 16;
    int wn = (wid >> 1) * 64;

    {
        size_t qb = ((size_t)(b * HH + h) * SS + q0) * HD;
        int row = tid >> 3, c8 = (tid & 7) * 8;
        *(uint4*)(dynsm + SC_Q + (row * 72 + c8) * 2) = *(const uint4*)&q[qb + row * 64 + c8];
    }

    auto load_k = [&](int st, int kt) {
        uint32_t kb = smbase + SC_K + st * SC_KSTAGE;
        size_t gb = ((size_t)(b * HH + h) * SS + kt) * HD;
        #pragma unroll
        for (int it = 0; it < 8; it++) {
            int idx = tid + it * 256;
            int row = idx >> 3, c8 = (idx & 7) * 8;
            cpa16(kb + (uint32_t)(row * 72 + c8) * 2, k + gb + (size_t)row * 64 + c8);
        }
        cp_commit();
    };
    load_k(0, 0);
    load_k(1, 256);

    uint32_t aq_off = (uint32_t)((wm + (lane & 15)) * 72 + (lane >> 4) * 8) * 2;
    int rr_ = lane & 7, halfk = (lane >> 3) & 1, q2 = lane >> 4;

    for (int i = 0; i < 4; i++) {
        if (i < 3) cp_wait<1>(); else cp_wait<0>();
        __syncthreads();
        uint32_t kb = smbase + SC_K + (i & 1) * SC_KSTAGE;

        float acc[8][4];
        #pragma unroll
        for (int a = 0; a < 8; a++)
            #pragma unroll
            for (int c = 0; c < 4; c++) acc[a][c] = 0.f;

        #pragma unroll
        for (int ks = 0; ks < 4; ks++) {
            uint32_t ahf[4];
            ldsm_x4(ahf, smbase + SC_Q + aq_off + ks * 32);
            uint32_t bhf[4][4];
            #pragma unroll
            for (int nb = 0; nb < 4; nb++) {
                uint32_t boff = (uint32_t)((wn + nb * 16 + q2 * 8 + rr_) * 72 + halfk * 8 + ks * 16) * 2;
                ldsm_x4(bhf[nb], kb + boff);
            }
            #pragma unroll
            for (int nb = 0; nb < 4; nb++) {
                mma16816(acc[nb*2],   ahf, bhf[nb]);
                mma16816(acc[nb*2+1], ahf, bhf[nb] + 2);
            }
        }

        int kt = i * 256;
        int group = lane >> 2, tig = lane & 3;
        #pragma unroll
        for (int ni = 0; ni < 8; ni++) {
            int row = wm + group;
            int col = kt + wn + ni * 8 + tig * 2;
            *(float2*)&Ssc[row * 1032 + col] =
                make_float2(acc[ni][0] * QSCALE, acc[ni][1] * QSCALE);
            *(float2*)&Ssc[(row + 8) * 1032 + col] =
                make_float2(acc[ni][2] * QSCALE, acc[ni][3] * QSCALE);
        }
        __syncthreads();
        if (i + 2 < 4) load_k((i + 2) & 1, (i + 2) * 256);
    }

    for (int rr = 0; rr < 4; rr++) {
        int row = wid * 4 + rr;
        float2 v2[16];
        float m = -1e30f;
        #pragma unroll
        for (int i2 = 0; i2 < 16; i2++) {
            v2[i2] = *(float2*)&Ssc[row * 1032 + (lane + i2 * 32) * 2];
            m = fmaxf(m, fmaxf(v2[i2].x, v2[i2].y));
        }
        #pragma unroll
        for (int o = 16; o; o >>= 1) m = fmaxf(m, __shfl_xor_sync(0xffffffffu, m, o));
        float s = 0.f;
        #pragma unroll
        for (int i2 = 0; i2 < 16; i2++) {
            v2[i2].x = __expf(v2[i2].x - m);
            v2[i2].y = __expf(v2[i2].y - m);
            s += v2[i2].x + v2[i2].y;
        }
        #pragma unroll
        for (int o = 16; o; o >>= 1) s += __shfl_xor_sync(0xffffffffu, s, o);
        float inv = 1.f / s;
        size_t gb = ((size_t)(b * HH + h) * SS + q0 + row) * SS;
        #pragma unroll
        for (int i2 = 0; i2 < 16; i2++) {
            size_t o = gb + (size_t)(lane + i2 * 32) * 2;
            *(__half2*)&P[o] = __halves2half2(
                __float2half_rn(v2[i2].x * inv), __float2half_rn(v2[i2].y * inv));
        }
    }
}

// ---------------------------------------------------------------------------
// PV: AO = P @ V per (b,h,256q). 1-pass fp16. AO hi-only.
// ---------------------------------------------------------------------------
#define PV_P  0
#define PV_VH 36864
#define PV_STAGE 46080
#define PV_SMEM 92160

__global__ __launch_bounds__(256) void attn_pv_mma(
    const __half* __restrict__ P, const __half* __restrict__ v,
    __half* __restrict__ AO)
{
    extern __shared__ char dynsm[];
    uint32_t smbase = (uint32_t)__cvta_generic_to_shared(dynsm);

    int b = blockIdx.z, h = blockIdx.y, q0 = blockIdx.x * 256;
    int tid = threadIdx.x, lane = tid & 31, wid = tid >> 5;

    auto load_stage = [&](int st, int kt) {
        uint32_t sb = smbase + st * PV_STAGE;
        size_t pb = ((size_t)(b * HH + h) * SS + q0) * SS + kt;
        #pragma unroll
        for (int it = 0; it < 8; it++) {
            int idx = tid + it * 256;
            int row = idx >> 3, c8 = (idx & 7) * 8;
            cpa16(sb + PV_P + (uint32_t)(row * 72 + c8) * 2, P + pb + (size_t)row * SS + c8);
        }
        size_t vb = ((size_t)(b * HH + h) * SS + kt) * HD;
        #pragma unroll
        for (int it = 0; it < 2; it++) {
            int idx = tid + it * 256;
            int row = idx >> 3, c8 = (idx & 7) * 8;
            cpa16(sb + PV_VH + (uint32_t)(row * 72 + c8) * 2, v + vb + row * 64 + c8);
        }
        cp_commit();
    };

    float acc[2][8][4];
    #pragma unroll
    for (int a = 0; a < 2; a++)
        #pragma unroll
        for (int j = 0; j < 8; j++)
            #pragma unroll
            for (int c = 0; c < 4; c++) acc[a][j][c] = 0.f;

    uint32_t ap_off = (uint32_t)((wid * 32 + (lane & 15)) * 72 + (lane >> 4) * 8) * 2;
    uint32_t bv_off = (uint32_t)((lane & 15) * 72) * 2;

    load_stage(0, 0);
    load_stage(1, 64);

    for (int i = 0; i < 16; i++) {
        if (i < 15) cp_wait<1>(); else cp_wait<0>();
        __syncthreads();
        uint32_t sb = smbase + (i & 1) * PV_STAGE;
        #pragma unroll
        for (int ks = 0; ks < 4; ks++) {
            uint32_t ahf[2][4];
            #pragma unroll
            for (int mi = 0; mi < 2; mi++) {
                uint32_t off = ap_off + (uint32_t)(mi * 16 * 72 + ks * 16) * 2;
                ldsm_x4(ahf[mi], sb + PV_P + off);
            }
            #pragma unroll
            for (int nb = 0; nb < 2; nb++) {
                uint32_t bhf[4][2];
                #pragma unroll
                for (int nj = 0; nj < 4; nj++) {
                    uint32_t off = bv_off + (uint32_t)(ks * 16 * 72 + (nb * 4 + nj) * 8) * 2;
                    ldsm_x2t(bhf[nj], sb + PV_VH + off);
                }
                #pragma unroll
                for (int nj = 0; nj < 4; nj++)
                    #pragma unroll
                    for (int mi = 0; mi < 2; mi++)
                        mma16816(acc[mi][nb*4+nj], ahf[mi], bhf[nj]);
            }
        }
        __syncthreads();
        if (i + 2 < 16) load_stage((i + 2) & 1, (i + 2) * 64);
    }

    int group = lane >> 2, tig = lane & 3;
    #pragma unroll
    for (int mi = 0; mi < 2; mi++) {
        #pragma unroll
        for (int ni = 0; ni < 8; ni++) {
            int d = ni * 8 + tig * 2;
            int r0 = q0 + wid * 32 + mi * 16 + group;
            size_t o0 = (size_t)(b * SS + r0) * DD + h * HD + d;
            size_t o1 = o0 + (size_t)8 * DD;
            *(__half2*)&AO[o0] = __halves2half2(
                __float2half_rn(acc[mi][ni][0]), __float2half_rn(acc[mi][ni][1]));
            *(__half2*)&AO[o1] = __halves2half2(
                __float2half_rn(acc[mi][ni][2]), __float2half_rn(acc[mi][ni][3]));
        }
    }
}

// ---------------------------------------------------------------------------
// attn_mean[b,q,k] = (1/H) * sum_h P
// ---------------------------------------------------------------------------
__global__ __launch_bounds__(256) void attn_mean_kernel(
    const __half* __restrict__ P, float* __restrict__ outm)
{
    size_t g = (size_t)blockIdx.x * 256 + threadIdx.x;
    int k8 = (int)(g & 127);
    size_t t = g >> 7;
    int q = (int)(t & 1023);
    int b = (int)(t >> 10);
    size_t k = (size_t)k8 * 8;

    float acc8[8];
    #pragma unroll
    for (int j = 0; j < 8; j++) acc8[j] = 0.f;
    #pragma unroll
    for (int h = 0; h < HH; h++) {
        size_t off = ((size_t)(b * HH + h) * SS + q) * SS + k;
        uint4 v4 = *(const uint4*)&P[off];
        const uint32_t* p = (const uint32_t*)&v4;
        #pragma unroll
        for (int j = 0; j < 4; j++) {
            float2 hh = __half22float2(*(__half2*)&p[j]);
            acc8[2*j]   += hh.x;
            acc8[2*j+1] += hh.y;
        }
    }
    size_t ob = ((size_t)(b * SS + q)) * SS + k;
    const float inv = 1.0f / HH;
    float4 o0 = make_float4(acc8[0]*inv, acc8[1]*inv, acc8[2]*inv, acc8[3]*inv);
    float4 o1 = make_float4(acc8[4]*inv, acc8[5]*inv, acc8[6]*inv, acc8[7]*inv);
    *(float4*)&outm[ob]     = o0;
    *(float4*)&outm[ob + 4] = o1;
}

// ---------------------------------------------------------------------------
// Host launcher (legal fork-join: s1 always forked via event from stream 0)
// ---------------------------------------------------------------------------
extern "C" void kernel_launch(void* const* d_in, const int* in_sizes, int n_in,
                              void* d_out, int out_size)
{
    const float* x     = (const float*)d_in[0];
    const float* w_in  = (const float*)d_in[1];
    const float* b_in  = (const float*)d_in[2];
    const float* w_out = (const float*)d_in[3];
    const float* b_out = (const float*)d_in[4];
    float* out = (float*)d_out;

    __half *xh, *wih, *woh;
    __half *q, *k, *v, *p, *ao;
    cudaGetSymbolAddress((void**)&xh,  g_xh);
    cudaGetSymbolAddress((void**)&wih, g_wih);
    cudaGetSymbolAddress((void**)&woh, g_woh);
    cudaGetSymbolAddress((void**)&q,   g_q);
    cudaGetSymbolAddress((void**)&k,   g_k);
    cudaGetSymbolAddress((void**)&v,   g_v);
    cudaGetSymbolAddress((void**)&p,   g_p);
    cudaGetSymbolAddress((void**)&ao,  g_ao);

    static cudaStream_t s1 = nullptr;
    static cudaEvent_t ev0 = nullptr, evA = nullptr, evB = nullptr, evC = nullptr;
    if (!s1) {
        cudaStreamCreateWithFlags(&s1, cudaStreamNonBlocking);
        cudaEventCreateWithFlags(&ev0, cudaEventDisableTiming);
        cudaEventCreateWithFlags(&evA, cudaEventDisableTiming);
        cudaEventCreateWithFlags(&evB, cudaEventDisableTiming);
        cudaEventCreateWithFlags(&evC, cudaEventDisableTiming);
    }

    cudaFuncSetAttribute(mma_gemm_qkv,
                         cudaFuncAttributeMaxDynamicSharedMemorySize, GEMM_SMEM);
    cudaFuncSetAttribute(mma_gemm_out,
                         cudaFuncAttributeMaxDynamicSharedMemorySize, GEMM_SMEM);
    cudaFuncSetAttribute(attn_scores_mma,
                         cudaFuncAttributeMaxDynamicSharedMemorySize, SC_SMEM);
    cudaFuncSetAttribute(attn_pv_mma,
                         cudaFuncAttributeMaxDynamicSharedMemorySize, PV_SMEM);

    // Legal fork: record on origin stream FIRST, then s1 waits on it.
    cudaEventRecord(ev0, 0);
    cudaStreamWaitEvent(s1, ev0, 0);

    // 0. hi-only converts; w_out conversion hidden on side stream
    cvt_kernel<<<(MROWS * DD / 4 + 255) / 256, 256>>>(x, xh, MROWS * DD / 4);
    cvt_kernel<<<(DD * 3 * DD / 4 + 255) / 256, 256>>>(w_in, wih, DD * 3 * DD / 4);
    cvt_kernel<<<(DD * DD / 4 + 255) / 256, 256, 0, s1>>>(w_out, woh, DD * DD / 4);
    cudaEventRecord(evC, s1);

    // 1. QKV GEMM (1-pass) -> fp16 q/k/v per head
    mma_gemm_qkv<<<dim3(3 * DD / 128, MROWS / 128), 128, GEMM_SMEM>>>(
        xh, wih, b_in, q, k, v, MROWS, 3 * DD, DD);

    // 2. scores (1-pass) + softmax -> hi-only fp16 P
    attn_scores_mma<<<dim3(SS / 32, HH, BB), 256, SC_SMEM>>>(q, k, p);

    // fork: head-mean on side stream, overlapping PV + out-proj
    cudaEventRecord(evA, 0);
    cudaStreamWaitEvent(s1, evA, 0);
    attn_mean_kernel<<<(BB * SS * SS / 8) / 256, 256, 0, s1>>>(
        p, out + (size_t)BB * SS * SS);
    cudaEventRecord(evB, s1);

    // 3. P @ V (1-pass) -> hi-only fp16 AO
    attn_pv_mma<<<dim3(SS / 256, HH, BB), 256, PV_SMEM>>>(p, v, ao);

    // 4. output projection (1-pass), gated on w_out convert
    cudaStreamWaitEvent(0, evC, 0);
    mma_gemm_out<<<dim3(DD / 128, MROWS / 128), 128, GEMM_SMEM>>>(
        ao, woh, b_out, out, MROWS, DD, DD);

    // join
    cudaStreamWaitEvent(0, evB, 0);
}

// round 16
// speedup vs baseline: 1.8817x; 1.0109x over previous
#include <cuda_runtime.h>
#include <cuda_fp16.h>
#include <cstdint>

// Problem constants
#define BB 4
#define SS 1024
#define DD 1024
#define HH 16
#define HD 64
#define MROWS (BB*SS)          // 4096
#define QSCALE 0.03125f        // 1024^-0.5

// ---------------------------------------------------------------------------
// Scratch (all fp16 hi-only)
// ---------------------------------------------------------------------------
__device__ __half g_xh[(size_t)MROWS * DD];
__device__ __half g_wih[(size_t)DD * 3 * DD];
__device__ __half g_woh[(size_t)DD * DD];
__device__ __half g_q[(size_t)BB*HH*SS*HD];
__device__ __half g_k[(size_t)BB*HH*SS*HD];
__device__ __half g_v[(size_t)BB*HH*SS*HD];
__device__ __half g_p[(size_t)BB*HH*SS*SS];
__device__ __half g_ao[(size_t)MROWS * DD];

// ---------------------------------------------------------------------------
// MMA / ldmatrix / cp.async helpers (fp16)
// ---------------------------------------------------------------------------
__device__ __forceinline__ void mma16816(float* d, const uint32_t* a, const uint32_t* b) {
    asm volatile(
        "mma.sync.aligned.m16n8k16.row.col.f32.f16.f16.f32 "
        "{%0,%1,%2,%3}, {%4,%5,%6,%7}, {%8,%9}, {%0,%1,%2,%3};"
        : "+f"(d[0]), "+f"(d[1]), "+f"(d[2]), "+f"(d[3])
        : "r"(a[0]), "r"(a[1]), "r"(a[2]), "r"(a[3]), "r"(b[0]), "r"(b[1]));
}
__device__ __forceinline__ void ldsm_x4(uint32_t* r, uint32_t addr) {
    asm volatile("ldmatrix.sync.aligned.m8n8.x4.shared.b16 {%0,%1,%2,%3}, [%4];"
                 : "=r"(r[0]), "=r"(r[1]), "=r"(r[2]), "=r"(r[3]) : "r"(addr));
}
__device__ __forceinline__ void ldsm_x2t(uint32_t* r, uint32_t addr) {
    asm volatile("ldmatrix.sync.aligned.m8n8.x2.trans.shared.b16 {%0,%1}, [%2];"
                 : "=r"(r[0]), "=r"(r[1]) : "r"(addr));
}
__device__ __forceinline__ void cpa16(uint32_t s, const void* g) {
    asm volatile("cp.async.cg.shared.global [%0], [%1], 16;" :: "r"(s), "l"(g));
}
__device__ __forceinline__ void cp_commit() { asm volatile("cp.async.commit_group;"); }
template<int N> __device__ __forceinline__ void cp_wait() {
    asm volatile("cp.async.wait_group %0;" :: "n"(N));
}

// ---------------------------------------------------------------------------
// hi-only convert: fp32 -> fp16
// ---------------------------------------------------------------------------
__global__ __launch_bounds__(256) void cvt_kernel(
    const float* __restrict__ in, __half* __restrict__ hi, int n4)
{
    int i = blockIdx.x * 256 + threadIdx.x;
    if (i >= n4) return;
    float4 v = ((const float4*)in)[i];
    ((__half2*)hi)[2 * i]     = __halves2half2(__float2half_rn(v.x), __float2half_rn(v.y));
    ((__half2*)hi)[2 * i + 1] = __halves2half2(__float2half_rn(v.z), __float2half_rn(v.w));
}

// ---------------------------------------------------------------------------
// GEMM tile (BM=BN=128, BK=32): 4 warps, warp tile 64x64. 1-pass fp16.
// 3-stage cp.async pipeline. bxoff/byoff allow grid slicing.
// ---------------------------------------------------------------------------
#define ASTR 40
#define BSTR 136
#define AH_OFF 0
#define BH_OFF 10240
#define STAGE_B 18944
#define GEMM_SMEM (STAGE_B * 3)

#define GEMM_PROLOG \
    extern __shared__ char dynsm[]; \
    uint32_t smbase = (uint32_t)__cvta_generic_to_shared(dynsm); \
    int bx = blockIdx.x + bxoff, by = blockIdx.y + byoff; \
    int tid = threadIdx.x, lane = tid & 31, wid = tid >> 5; \
    int wm = (wid & 1) * 64, wn = (wid >> 1) * 64; \
    uint32_t a_off = (uint32_t)((wm + (lane & 15)) * ASTR + (lane >> 4) * 8) * 2; \
    uint32_t b_off = (uint32_t)((lane & 15) * BSTR + wn) * 2; \
    float acc[4][8][4]; \
    _Pragma("unroll") for (int i = 0; i < 4; i++) \
        _Pragma("unroll") for (int j = 0; j < 8; j++) \
            _Pragma("unroll") for (int c = 0; c < 4; c++) acc[i][j][c] = 0.f; \
    const int nk = K >> 5; \
    auto load_stage = [&](int st, int kt) { \
        uint32_t sb = smbase + st * STAGE_B; \
        _Pragma("unroll") for (int i = 0; i < 4; i++) { \
            int row = (tid >> 2) + i * 32; \
            size_t g = (size_t)(by * 128 + row) * K + kt + (tid & 3) * 8; \
            cpa16(sb + AH_OFF + (uint32_t)(row * ASTR + (tid & 3) * 8) * 2, Ahg + g); \
        } \
        _Pragma("unroll") for (int i = 0; i < 4; i++) { \
            int row = (tid >> 4) + i * 8; \
            size_t g = (size_t)(kt + row) * N + bx * 128 + (tid & 15) * 8; \
            cpa16(sb + BH_OFF + (uint32_t)(row * BSTR + (tid & 15) * 8) * 2, Bhg + g); \
        } \
        cp_commit(); \
    }; \
    load_stage(0, 0); \
    load_stage(1, 32); \
    for (int i = 0; i < nk; i++) { \
        if (i + 1 < nk) cp_wait<1>(); else cp_wait<0>(); \
        __syncthreads(); \
        if (i + 2 < nk) load_stage((i + 2) % 3, (i + 2) * 32); \
        uint32_t sb = smbase + (i % 3) * STAGE_B; \
        _Pragma("unroll") for (int ks = 0; ks < 2; ks++) { \
            uint32_t ahf[4][4]; \
            _Pragma("unroll") for (int mi = 0; mi < 4; mi++) { \
                uint32_t off = a_off + (uint32_t)(mi * 16 * ASTR + ks * 16) * 2; \
                ldsm_x4(ahf[mi], sb + AH_OFF + off); \
            } \
            _Pragma("unroll") for (int nb = 0; nb < 2; nb++) { \
                uint32_t bhf[4][2]; \
                _Pragma("unroll") for (int nj = 0; nj < 4; nj++) { \
                    uint32_t off = b_off + (uint32_t)(ks * 16 * BSTR + (nb * 4 + nj) * 8) * 2; \
                    ldsm_x2t(bhf[nj], sb + BH_OFF + off); \
                } \
                _Pragma("unroll") for (int nj = 0; nj < 4; nj++) \
                    _Pragma("unroll") for (int mi = 0; mi < 4; mi++) \
                        mma16816(acc[mi][nb * 4 + nj], ahf[mi], bhf[nj]); \
            } \
        } \
    } \
    __syncthreads();

// ---------------------------------------------------------------------------
// QKV GEMM (1-pass): bxoff slices q/k (bx<16) vs v (bx>=16)
// ---------------------------------------------------------------------------
__global__ __launch_bounds__(128, 2) void mma_gemm_qkv(
    const __half* __restrict__ Ahg, const __half* __restrict__ Bhg,
    const float* __restrict__ bias,
    __half* __restrict__ q, __half* __restrict__ k, __half* __restrict__ v,
    int M, int N, int K, int bxoff)
{
    const int byoff = 0;
    GEMM_PROLOG

    int part = (bx * 128) >> 10;
    __half* dst = part == 0 ? q : (part == 1 ? k : v);
    int head = ((bx * 128 + wn) & 1023) >> 6;
    int bq = (by * 128) >> 10;
    int group = lane >> 2, tig = lane & 3;
    #pragma unroll
    for (int mi = 0; mi < 4; mi++) {
        int s0 = ((by * 128) & 1023) + wm + mi * 16 + group;
        #pragma unroll
        for (int ni = 0; ni < 8; ni++) {
            int col = bx * 128 + wn + ni * 8 + tig * 2;
            int d = ni * 8 + tig * 2;
            float b0 = bias[col], b1 = bias[col + 1];
            float v00 = acc[mi][ni][0] + b0, v01 = acc[mi][ni][1] + b1;
            float v10 = acc[mi][ni][2] + b0, v11 = acc[mi][ni][3] + b1;
            size_t o0 = ((size_t)(bq * HH + head) * SS + s0) * HD + d;
            size_t o1 = o0 + 8 * HD;
            *(__half2*)&dst[o0] = __halves2half2(__float2half_rn(v00), __float2half_rn(v01));
            *(__half2*)&dst[o1] = __halves2half2(__float2half_rn(v10), __float2half_rn(v11));
        }
    }
}

// ---------------------------------------------------------------------------
// Out-projection GEMM (1-pass): byoff slices row halves
// ---------------------------------------------------------------------------
__global__ __launch_bounds__(128, 2) void mma_gemm_out(
    const __half* __restrict__ Ahg, const __half* __restrict__ Bhg,
    const float* __restrict__ bias, float* __restrict__ C,
    int M, int N, int K, int byoff)
{
    const int bxoff = 0;
    GEMM_PROLOG

    int group = lane >> 2, tig = lane & 3;
    #pragma unroll
    for (int mi = 0; mi < 4; mi++) {
        int row0 = by * 128 + wm + mi * 16 + group;
        #pragma unroll
        for (int ni = 0; ni < 8; ni++) {
            int col = bx * 128 + wn + ni * 8 + tig * 2;
            float b0 = bias[col], b1 = bias[col + 1];
            *(float2*)&C[(size_t)row0 * N + col] =
                make_float2(acc[mi][ni][0] + b0, acc[mi][ni][1] + b1);
            *(float2*)&C[(size_t)(row0 + 8) * N + col] =
                make_float2(acc[mi][ni][2] + b0, acc[mi][ni][3] + b1);
        }
    }
}

// ---------------------------------------------------------------------------
// Scores + softmax: per (b,h,32q). Register-resident scores (no Ssc buffer).
// acc[4 chunks][8][4] holds the full 32x1024 tile across the CTA. Softmax via
// quad shuffles + 1KB cross-warp reduction. P written straight from regs.
// smem: K 2-stage [256][72] @0 | Q [32][72] @73728 | rmax/rsum @78336
// ---------------------------------------------------------------------------
#define SC_K      0
#define SC_KSTAGE 36864
#define SC_Q      73728
#define SC_RMAX   78336
#define SC_RSUM   78848
#define SC_SMEM   79360

__global__ __launch_bounds__(256) void attn_scores_mma(
    const __half* __restrict__ q, const __half* __restrict__ k,
    __half* __restrict__ P)
{
    extern __shared__ char dynsm[];
    uint32_t smbase = (uint32_t)__cvta_generic_to_shared(dynsm);
    float* rmax = (float*)(dynsm + SC_RMAX);
    float* rsum = (float*)(dynsm + SC_RSUM);

    int b = blockIdx.z, h = blockIdx.y, q0 = blockIdx.x * 32;
    int tid = threadIdx.x, lane = tid & 31, wid = tid >> 5;
    int wm = (wid & 1) * 16;
    int wn = (wid >> 1) * 64;

    {
        size_t qb = ((size_t)(b * HH + h) * SS + q0) * HD;
        int row = tid >> 3, c8 = (tid & 7) * 8;
        *(uint4*)(dynsm + SC_Q + (row * 72 + c8) * 2) = *(const uint4*)&q[qb + row * 64 + c8];
    }

    auto load_k = [&](int st, int kt) {
        uint32_t kb = smbase + SC_K + st * SC_KSTAGE;
        size_t gb = ((size_t)(b * HH + h) * SS + kt) * HD;
        #pragma unroll
        for (int it = 0; it < 8; it++) {
            int idx = tid + it * 256;
            int row = idx >> 3, c8 = (idx & 7) * 8;
            cpa16(kb + (uint32_t)(row * 72 + c8) * 2, k + gb + (size_t)row * 64 + c8);
        }
        cp_commit();
    };
    load_k(0, 0);
    load_k(1, 256);

    uint32_t aq_off = (uint32_t)((wm + (lane & 15)) * 72 + (lane >> 4) * 8) * 2;
    int rr_ = lane & 7, halfk = (lane >> 3) & 1, q2 = lane >> 4;

    float acc[4][8][4];
    #pragma unroll
    for (int c = 0; c < 4; c++)
        #pragma unroll
        for (int a = 0; a < 8; a++)
            #pragma unroll
            for (int e = 0; e < 4; e++) acc[c][a][e] = 0.f;

    for (int ch = 0; ch < 4; ch++) {
        if (ch < 3) cp_wait<1>(); else cp_wait<0>();
        __syncthreads();
        uint32_t kb = smbase + SC_K + (ch & 1) * SC_KSTAGE;

        #pragma unroll
        for (int ks = 0; ks < 4; ks++) {
            uint32_t ahf[4];
            ldsm_x4(ahf, smbase + SC_Q + aq_off + ks * 32);
            uint32_t bhf[4][4];
            #pragma unroll
            for (int nb = 0; nb < 4; nb++) {
                uint32_t boff = (uint32_t)((wn + nb * 16 + q2 * 8 + rr_) * 72 + halfk * 8 + ks * 16) * 2;
                ldsm_x4(bhf[nb], kb + boff);
            }
            #pragma unroll
            for (int nb = 0; nb < 4; nb++) {
                mma16816(acc[ch][nb*2],   ahf, bhf[nb]);
                mma16816(acc[ch][nb*2+1], ahf, bhf[nb] + 2);
            }
        }
        __syncthreads();
        if (ch + 2 < 4) load_k((ch + 2) & 1, (ch + 2) * 256);
    }

    // ---- register-resident softmax ----
    int tig = lane & 3, group = lane >> 2;
    int r0 = wm + group, r1 = r0 + 8;
    int wq = wid >> 1;

    float m0 = -1e30f, m1 = -1e30f;
    #pragma unroll
    for (int c = 0; c < 4; c++)
        #pragma unroll
        for (int a = 0; a < 8; a++) {
            m0 = fmaxf(m0, fmaxf(acc[c][a][0], acc[c][a][1]));
            m1 = fmaxf(m1, fmaxf(acc[c][a][2], acc[c][a][3]));
        }
    #pragma unroll
    for (int o = 1; o <= 2; o <<= 1) {
        m0 = fmaxf(m0, __shfl_xor_sync(0xffffffffu, m0, o));
        m1 = fmaxf(m1, __shfl_xor_sync(0xffffffffu, m1, o));
    }
    if (tig == 0) { rmax[r0 * 4 + wq] = m0; rmax[r1 * 4 + wq] = m1; }
    __syncthreads();
    float M0 = fmaxf(fmaxf(rmax[r0*4], rmax[r0*4+1]), fmaxf(rmax[r0*4+2], rmax[r0*4+3]));
    float M1 = fmaxf(fmaxf(rmax[r1*4], rmax[r1*4+1]), fmaxf(rmax[r1*4+2], rmax[r1*4+3]));

    float s0 = 0.f, s1 = 0.f;
    #pragma unroll
    for (int c = 0; c < 4; c++)
        #pragma unroll
        for (int a = 0; a < 8; a++) {
            acc[c][a][0] = __expf((acc[c][a][0] - M0) * QSCALE);
            acc[c][a][1] = __expf((acc[c][a][1] - M0) * QSCALE);
            acc[c][a][2] = __expf((acc[c][a][2] - M1) * QSCALE);
            acc[c][a][3] = __expf((acc[c][a][3] - M1) * QSCALE);
            s0 += acc[c][a][0] + acc[c][a][1];
            s1 += acc[c][a][2] + acc[c][a][3];
        }
    #pragma unroll
    for (int o = 1; o <= 2; o <<= 1) {
        s0 += __shfl_xor_sync(0xffffffffu, s0, o);
        s1 += __shfl_xor_sync(0xffffffffu, s1, o);
    }
    if (tig == 0) { rsum[r0 * 4 + wq] = s0; rsum[r1 * 4 + wq] = s1; }
    __syncthreads();
    float inv0 = 1.f / (rsum[r0*4] + rsum[r0*4+1] + rsum[r0*4+2] + rsum[r0*4+3]);
    float inv1 = 1.f / (rsum[r1*4] + rsum[r1*4+1] + rsum[r1*4+2] + rsum[r1*4+3]);

    size_t gb0 = ((size_t)(b * HH + h) * SS + q0 + r0) * SS;
    size_t gb1 = gb0 + (size_t)8 * SS;
    #pragma unroll
    for (int c = 0; c < 4; c++)
        #pragma unroll
        for (int a = 0; a < 8; a++) {
            int col = c * 256 + wn + a * 8 + tig * 2;
            *(__half2*)&P[gb0 + col] = __halves2half2(
                __float2half_rn(acc[c][a][0] * inv0), __float2half_rn(acc[c][a][1] * inv0));
            *(__half2*)&P[gb1 + col] = __halves2half2(
                __float2half_rn(acc[c][a][2] * inv1), __float2half_rn(acc[c][a][3] * inv1));
        }
}

// ---------------------------------------------------------------------------
// PV: AO = P @ V per (b,h,256q). 1-pass fp16. b0 slices batch halves.
// ---------------------------------------------------------------------------
#define PV_P  0
#define PV_VH 36864
#define PV_STAGE 46080
#define PV_SMEM 92160

__global__ __launch_bounds__(256) void attn_pv_mma(
    const __half* __restrict__ P, const __half* __restrict__ v,
    __half* __restrict__ AO, int b0)
{
    extern __shared__ char dynsm[];
    uint32_t smbase = (uint32_t)__cvta_generic_to_shared(dynsm);

    int b = blockIdx.z + b0, h = blockIdx.y, q0 = blockIdx.x * 256;
    int tid = threadIdx.x, lane = tid & 31, wid = tid >> 5;

    auto load_stage = [&](int st, int kt) {
        uint32_t sb = smbase + st * PV_STAGE;
        size_t pb = ((size_t)(b * HH + h) * SS + q0) * SS + kt;
        #pragma unroll
        for (int it = 0; it < 8; it++) {
            int idx = tid + it * 256;
            int row = idx >> 3, c8 = (idx & 7) * 8;
            cpa16(sb + PV_P + (uint32_t)(row * 72 + c8) * 2, P + pb + (size_t)row * SS + c8);
        }
        size_t vb = ((size_t)(b * HH + h) * SS + kt) * HD;
        #pragma unroll
        for (int it = 0; it < 2; it++) {
            int idx = tid + it * 256;
            int row = idx >> 3, c8 = (idx & 7) * 8;
            cpa16(sb + PV_VH + (uint32_t)(row * 72 + c8) * 2, v + vb + row * 64 + c8);
        }
        cp_commit();
    };

    float acc[2][8][4];
    #pragma unroll
    for (int a = 0; a < 2; a++)
        #pragma unroll
        for (int j = 0; j < 8; j++)
            #pragma unroll
            for (int c = 0; c < 4; c++) acc[a][j][c] = 0.f;

    uint32_t ap_off = (uint32_t)((wid * 32 + (lane & 15)) * 72 + (lane >> 4) * 8) * 2;
    uint32_t bv_off = (uint32_t)((lane & 15) * 72) * 2;

    load_stage(0, 0);
    load_stage(1, 64);

    for (int i = 0; i < 16; i++) {
        if (i < 15) cp_wait<1>(); else cp_wait<0>();
        __syncthreads();
        uint32_t sb = smbase + (i & 1) * PV_STAGE;
        #pragma unroll
        for (int ks = 0; ks < 4; ks++) {
            uint32_t ahf[2][4];
            #pragma unroll
            for (int mi = 0; mi < 2; mi++) {
                uint32_t off = ap_off + (uint32_t)(mi * 16 * 72 + ks * 16) * 2;
                ldsm_x4(ahf[mi], sb + PV_P + off);
            }
            #pragma unroll
            for (int nb = 0; nb < 2; nb++) {
                uint32_t bhf[4][2];
                #pragma unroll
                for (int nj = 0; nj < 4; nj++) {
                    uint32_t off = bv_off + (uint32_t)(ks * 16 * 72 + (nb * 4 + nj) * 8) * 2;
                    ldsm_x2t(bhf[nj], sb + PV_VH + off);
                }
                #pragma unroll
                for (int nj = 0; nj < 4; nj++)
                    #pragma unroll
                    for (int mi = 0; mi < 2; mi++)
                        mma16816(acc[mi][nb*4+nj], ahf[mi], bhf[nj]);
            }
        }
        __syncthreads();
        if (i + 2 < 16) load_stage((i + 2) & 1, (i + 2) * 64);
    }

    int group = lane >> 2, tig = lane & 3;
    #pragma unroll
    for (int mi = 0; mi < 2; mi++) {
        #pragma unroll
        for (int ni = 0; ni < 8; ni++) {
            int d = ni * 8 + tig * 2;
            int r0 = q0 + wid * 32 + mi * 16 + group;
            size_t o0 = (size_t)(b * SS + r0) * DD + h * HD + d;
            size_t o1 = o0 + (size_t)8 * DD;
            *(__half2*)&AO[o0] = __halves2half2(
                __float2half_rn(acc[mi][ni][0]), __float2half_rn(acc[mi][ni][1]));
            *(__half2*)&AO[o1] = __halves2half2(
                __float2half_rn(acc[mi][ni][2]), __float2half_rn(acc[mi][ni][3]));
        }
    }
}

// ---------------------------------------------------------------------------
// attn_mean[b,q,k] = (1/H) * sum_h P
// ---------------------------------------------------------------------------
__global__ __launch_bounds__(256) void attn_mean_kernel(
    const __half* __restrict__ P, float* __restrict__ outm)
{
    size_t g = (size_t)blockIdx.x * 256 + threadIdx.x;
    int k8 = (int)(g & 127);
    size_t t = g >> 7;
    int q = (int)(t & 1023);
    int b = (int)(t >> 10);
    size_t k = (size_t)k8 * 8;

    float acc8[8];
    #pragma unroll
    for (int j = 0; j < 8; j++) acc8[j] = 0.f;
    #pragma unroll
    for (int h = 0; h < HH; h++) {
        size_t off = ((size_t)(b * HH + h) * SS + q) * SS + k;
        uint4 v4 = *(const uint4*)&P[off];
        const uint32_t* p = (const uint32_t*)&v4;
        #pragma unroll
        for (int j = 0; j < 4; j++) {
            float2 hh = __half22float2(*(__half2*)&p[j]);
            acc8[2*j]   += hh.x;
            acc8[2*j+1] += hh.y;
        }
    }
    size_t ob = ((size_t)(b * SS + q)) * SS + k;
    const float inv = 1.0f / HH;
    float4 o0 = make_float4(acc8[0]*inv, acc8[1]*inv, acc8[2]*inv, acc8[3]*inv);
    float4 o1 = make_float4(acc8[4]*inv, acc8[5]*inv, acc8[6]*inv, acc8[7]*inv);
    *(float4*)&outm[ob]     = o0;
    *(float4*)&outm[ob + 4] = o1;
}

// ---------------------------------------------------------------------------
// Host launcher: legal event-forked dual-stream schedule.
// s1: cvt w_out -> v-GEMM (overlaps qk/scores) -> out half0 (overlaps PV
// half1) -> mean (overlaps out half1). All s1 ops descend from ev0 fork.
// ---------------------------------------------------------------------------
extern "C" void kernel_launch(void* const* d_in, const int* in_sizes, int n_in,
                              void* d_out, int out_size)
{
    const float* x     = (const float*)d_in[0];
    const float* w_in  = (const float*)d_in[1];
    const float* b_in  = (const float*)d_in[2];
    const float* w_out = (const float*)d_in[3];
    const float* b_out = (const float*)d_in[4];
    float* out = (float*)d_out;

    __half *xh, *wih, *woh;
    __half *q, *k, *v, *p, *ao;
    cudaGetSymbolAddress((void**)&xh,  g_xh);
    cudaGetSymbolAddress((void**)&wih, g_wih);
    cudaGetSymbolAddress((void**)&woh, g_woh);
    cudaGetSymbolAddress((void**)&q,   g_q);
    cudaGetSymbolAddress((void**)&k,   g_k);
    cudaGetSymbolAddress((void**)&v,   g_v);
    cudaGetSymbolAddress((void**)&p,   g_p);
    cudaGetSymbolAddress((void**)&ao,  g_ao);

    static cudaStream_t s1 = nullptr;
    static cudaEvent_t ev0 = nullptr, evX = nullptr, evV = nullptr,
                       evA = nullptr, evP0 = nullptr, evB = nullptr;
    if (!s1) {
        cudaStreamCreateWithFlags(&s1, cudaStreamNonBlocking);
        cudaEventCreateWithFlags(&ev0, cudaEventDisableTiming);
        cudaEventCreateWithFlags(&evX, cudaEventDisableTiming);
        cudaEventCreateWithFlags(&evV, cudaEventDisableTiming);
        cudaEventCreateWithFlags(&evA, cudaEventDisableTiming);
        cudaEventCreateWithFlags(&evP0, cudaEventDisableTiming);
        cudaEventCreateWithFlags(&evB, cudaEventDisableTiming);
    }

    cudaFuncSetAttribute(mma_gemm_qkv,
                         cudaFuncAttributeMaxDynamicSharedMemorySize, GEMM_SMEM);
    cudaFuncSetAttribute(mma_gemm_out,
                         cudaFuncAttributeMaxDynamicSharedMemorySize, GEMM_SMEM);
    cudaFuncSetAttribute(attn_scores_mma,
                         cudaFuncAttributeMaxDynamicSharedMemorySize, SC_SMEM);
    cudaFuncSetAttribute(attn_pv_mma,
                         cudaFuncAttributeMaxDynamicSharedMemorySize, PV_SMEM);

    // fork s1 legally off the capture-origin stream
    cudaEventRecord(ev0, 0);
    cudaStreamWaitEvent(s1, ev0, 0);

    // main: converts for x and w_in
    cvt_kernel<<<(MROWS * DD / 4 + 255) / 256, 256>>>(x, xh, MROWS * DD / 4);
    cvt_kernel<<<(DD * 3 * DD / 4 + 255) / 256, 256>>>(w_in, wih, DD * 3 * DD / 4);
    cudaEventRecord(evX, 0);

    // s1: w_out convert, then v-part of QKV (overlaps qk-GEMM + scores)
    cvt_kernel<<<(DD * DD / 4 + 255) / 256, 256, 0, s1>>>(w_out, woh, DD * DD / 4);
    cudaStreamWaitEvent(s1, evX, 0);
    mma_gemm_qkv<<<dim3(8, MROWS / 128), 128, GEMM_SMEM, s1>>>(
        xh, wih, b_in, q, k, v, MROWS, 3 * DD, DD, 16);   // v third
    cudaEventRecord(evV, s1);

    // main: qk two-thirds of QKV
    mma_gemm_qkv<<<dim3(16, MROWS / 128), 128, GEMM_SMEM>>>(
        xh, wih, b_in, q, k, v, MROWS, 3 * DD, DD, 0);

    // main: scores (register-resident softmax)
    attn_scores_mma<<<dim3(SS / 32, HH, BB), 256, SC_SMEM>>>(q, k, p);
    cudaEventRecord(evA, 0);

    // main: PV half 0 (needs v)
    cudaStreamWaitEvent(0, evV, 0);
    attn_pv_mma<<<dim3(SS / 256, HH, 2), 256, PV_SMEM>>>(p, v, ao, 0);
    cudaEventRecord(evP0, 0);

    // main: PV half 1
    attn_pv_mma<<<dim3(SS / 256, HH, 2), 256, PV_SMEM>>>(p, v, ao, 2);

    // s1: out-proj rows 0..2047 (overlaps PV half 1), then mean
    cudaStreamWaitEvent(s1, evP0, 0);
    mma_gemm_out<<<dim3(8, 16), 128, GEMM_SMEM, s1>>>(
        ao, woh, b_out, out, MROWS, DD, DD, 0);
    cudaStreamWaitEvent(s1, evA, 0);
    attn_mean_kernel<<<(BB * SS * SS / 8) / 256, 256, 0, s1>>>(
        p, out + (size_t)BB * SS * SS);
    cudaEventRecord(evB, s1);

    // main: out-proj rows 2048..4095 (w_out ready via evV ordering on s1)
    mma_gemm_out<<<dim3(8, 16), 128, GEMM_SMEM>>>(
        ao, woh, b_out, out, MROWS, DD, DD, 16);

    // join
    cudaStreamWaitEvent(0, evB, 0);
}

// round 17
// speedup vs baseline: 1.9383x; 1.0301x over previous
#include <cuda_runtime.h>
#include <cuda_fp16.h>
#include <cstdint>

// Problem constants
#define BB 4
#define SS 1024
#define DD 1024
#define HH 16
#define HD 64
#define MROWS (BB*SS)          // 4096
#define QSCALE 0.03125f        // 1024^-0.5

// ---------------------------------------------------------------------------
// Scratch (all fp16 hi-only)
// ---------------------------------------------------------------------------
__device__ __half g_xh[(size_t)MROWS * DD];
__device__ __half g_wih[(size_t)DD * 3 * DD];
__device__ __half g_woh[(size_t)DD * DD];
__device__ __half g_q[(size_t)BB*HH*SS*HD];
__device__ __half g_k[(size_t)BB*HH*SS*HD];
__device__ __half g_v[(size_t)BB*HH*SS*HD];
__device__ __half g_p[(size_t)BB*HH*SS*SS];
__device__ __half g_ao[(size_t)MROWS * DD];

// ---------------------------------------------------------------------------
// MMA / ldmatrix / cp.async helpers (fp16)
// ---------------------------------------------------------------------------
__device__ __forceinline__ void mma16816(float* d, const uint32_t* a, const uint32_t* b) {
    asm volatile(
        "mma.sync.aligned.m16n8k16.row.col.f32.f16.f16.f32 "
        "{%0,%1,%2,%3}, {%4,%5,%6,%7}, {%8,%9}, {%0,%1,%2,%3};"
        : "+f"(d[0]), "+f"(d[1]), "+f"(d[2]), "+f"(d[3])
        : "r"(a[0]), "r"(a[1]), "r"(a[2]), "r"(a[3]), "r"(b[0]), "r"(b[1]));
}
__device__ __forceinline__ void ldsm_x4(uint32_t* r, uint32_t addr) {
    asm volatile("ldmatrix.sync.aligned.m8n8.x4.shared.b16 {%0,%1,%2,%3}, [%4];"
                 : "=r"(r[0]), "=r"(r[1]), "=r"(r[2]), "=r"(r[3]) : "r"(addr));
}
__device__ __forceinline__ void ldsm_x2t(uint32_t* r, uint32_t addr) {
    asm volatile("ldmatrix.sync.aligned.m8n8.x2.trans.shared.b16 {%0,%1}, [%2];"
                 : "=r"(r[0]), "=r"(r[1]) : "r"(addr));
}
__device__ __forceinline__ void cpa16(uint32_t s, const void* g) {
    asm volatile("cp.async.cg.shared.global [%0], [%1], 16;" :: "r"(s), "l"(g));
}
__device__ __forceinline__ void cp_commit() { asm volatile("cp.async.commit_group;"); }
template<int N> __device__ __forceinline__ void cp_wait() {
    asm volatile("cp.async.wait_group %0;" :: "n"(N));
}

// ---------------------------------------------------------------------------
// hi-only convert: fp32 -> fp16
// ---------------------------------------------------------------------------
__global__ __launch_bounds__(256) void cvt_kernel(
    const float* __restrict__ in, __half* __restrict__ hi, int n4)
{
    int i = blockIdx.x * 256 + threadIdx.x;
    if (i >= n4) return;
    float4 v = ((const float4*)in)[i];
    ((__half2*)hi)[2 * i]     = __halves2half2(__float2half_rn(v.x), __float2half_rn(v.y));
    ((__half2*)hi)[2 * i + 1] = __halves2half2(__float2half_rn(v.z), __float2half_rn(v.w));
}

// ---------------------------------------------------------------------------
// GEMM tile (BM=BN=128, BK=32): 256 threads, 8 warps (4m x 2n), warp 32x64.
// 1-pass fp16, 3-stage cp.async, 2 CTAs/SM (16 warps/SM for latency hiding).
// ---------------------------------------------------------------------------
#define ASTR 40
#define BSTR 136
#define AH_OFF 0
#define BH_OFF 10240
#define STAGE_B 18944
#define GEMM_SMEM (STAGE_B * 3)

#define GEMM_PROLOG \
    extern __shared__ char dynsm[]; \
    uint32_t smbase = (uint32_t)__cvta_generic_to_shared(dynsm); \
    int bx = blockIdx.x + bxoff, by = blockIdx.y + byoff; \
    int tid = threadIdx.x, lane = tid & 31, wid = tid >> 5; \
    int wm = (wid & 3) * 32, wn = (wid >> 2) * 64; \
    uint32_t a_off = (uint32_t)((wm + (lane & 15)) * ASTR + (lane >> 4) * 8) * 2; \
    uint32_t b_off = (uint32_t)((lane & 15) * BSTR + wn) * 2; \
    float acc[2][8][4]; \
    _Pragma("unroll") for (int i = 0; i < 2; i++) \
        _Pragma("unroll") for (int j = 0; j < 8; j++) \
            _Pragma("unroll") for (int c = 0; c < 4; c++) acc[i][j][c] = 0.f; \
    const int nk = K >> 5; \
    auto load_stage = [&](int st, int kt) { \
        uint32_t sb = smbase + st * STAGE_B; \
        _Pragma("unroll") for (int i = 0; i < 2; i++) { \
            int row = (tid >> 2) + i * 64; \
            size_t g = (size_t)(by * 128 + row) * K + kt + (tid & 3) * 8; \
            cpa16(sb + AH_OFF + (uint32_t)(row * ASTR + (tid & 3) * 8) * 2, Ahg + g); \
        } \
        _Pragma("unroll") for (int i = 0; i < 2; i++) { \
            int row = (tid >> 4) + i * 16; \
            size_t g = (size_t)(kt + row) * N + bx * 128 + (tid & 15) * 8; \
            cpa16(sb + BH_OFF + (uint32_t)(row * BSTR + (tid & 15) * 8) * 2, Bhg + g); \
        } \
        cp_commit(); \
    }; \
    load_stage(0, 0); \
    load_stage(1, 32); \
    for (int i = 0; i < nk; i++) { \
        if (i + 1 < nk) cp_wait<1>(); else cp_wait<0>(); \
        __syncthreads(); \
        if (i + 2 < nk) load_stage((i + 2) % 3, (i + 2) * 32); \
        uint32_t sb = smbase + (i % 3) * STAGE_B; \
        _Pragma("unroll") for (int ks = 0; ks < 2; ks++) { \
            uint32_t ahf[2][4]; \
            _Pragma("unroll") for (int mi = 0; mi < 2; mi++) { \
                uint32_t off = a_off + (uint32_t)(mi * 16 * ASTR + ks * 16) * 2; \
                ldsm_x4(ahf[mi], sb + AH_OFF + off); \
            } \
            _Pragma("unroll") for (int nb = 0; nb < 2; nb++) { \
                uint32_t bhf[4][2]; \
                _Pragma("unroll") for (int nj = 0; nj < 4; nj++) { \
                    uint32_t off = b_off + (uint32_t)(ks * 16 * BSTR + (nb * 4 + nj) * 8) * 2; \
                    ldsm_x2t(bhf[nj], sb + BH_OFF + off); \
                } \
                _Pragma("unroll") for (int nj = 0; nj < 4; nj++) \
                    _Pragma("unroll") for (int mi = 0; mi < 2; mi++) \
                        mma16816(acc[mi][nb * 4 + nj], ahf[mi], bhf[nj]); \
            } \
        } \
    } \
    __syncthreads();

// ---------------------------------------------------------------------------
// QKV GEMM (1-pass): bxoff slices q/k (bx<16) vs v (bx>=16)
// ---------------------------------------------------------------------------
__global__ __launch_bounds__(256, 2) void mma_gemm_qkv(
    const __half* __restrict__ Ahg, const __half* __restrict__ Bhg,
    const float* __restrict__ bias,
    __half* __restrict__ q, __half* __restrict__ k, __half* __restrict__ v,
    int M, int N, int K, int bxoff)
{
    const int byoff = 0;
    GEMM_PROLOG

    int part = (bx * 128) >> 10;
    __half* dst = part == 0 ? q : (part == 1 ? k : v);
    int head = ((bx * 128 + wn) & 1023) >> 6;
    int bq = (by * 128) >> 10;
    int group = lane >> 2, tig = lane & 3;
    #pragma unroll
    for (int mi = 0; mi < 2; mi++) {
        int s0 = ((by * 128) & 1023) + wm + mi * 16 + group;
        #pragma unroll
        for (int ni = 0; ni < 8; ni++) {
            int col = bx * 128 + wn + ni * 8 + tig * 2;
            int d = ni * 8 + tig * 2;
            float b0 = bias[col], b1 = bias[col + 1];
            float v00 = acc[mi][ni][0] + b0, v01 = acc[mi][ni][1] + b1;
            float v10 = acc[mi][ni][2] + b0, v11 = acc[mi][ni][3] + b1;
            size_t o0 = ((size_t)(bq * HH + head) * SS + s0) * HD + d;
            size_t o1 = o0 + 8 * HD;
            *(__half2*)&dst[o0] = __halves2half2(__float2half_rn(v00), __float2half_rn(v01));
            *(__half2*)&dst[o1] = __halves2half2(__float2half_rn(v10), __float2half_rn(v11));
        }
    }
}

// ---------------------------------------------------------------------------
// Out-projection GEMM (1-pass): byoff slices row halves
// ---------------------------------------------------------------------------
__global__ __launch_bounds__(256, 2) void mma_gemm_out(
    const __half* __restrict__ Ahg, const __half* __restrict__ Bhg,
    const float* __restrict__ bias, float* __restrict__ C,
    int M, int N, int K, int byoff)
{
    const int bxoff = 0;
    GEMM_PROLOG

    int group = lane >> 2, tig = lane & 3;
    #pragma unroll
    for (int mi = 0; mi < 2; mi++) {
        int row0 = by * 128 + wm + mi * 16 + group;
        #pragma unroll
        for (int ni = 0; ni < 8; ni++) {
            int col = bx * 128 + wn + ni * 8 + tig * 2;
            float b0 = bias[col], b1 = bias[col + 1];
            *(float2*)&C[(size_t)row0 * N + col] =
                make_float2(acc[mi][ni][0] + b0, acc[mi][ni][1] + b1);
            *(float2*)&C[(size_t)(row0 + 8) * N + col] =
                make_float2(acc[mi][ni][2] + b0, acc[mi][ni][3] + b1);
        }
    }
}

// ---------------------------------------------------------------------------
// Scores + softmax: per (b,h,32q). Register-resident scores.
// smem: K 2-stage [256][72] @0 | Q [32][72] @73728 | rmax/rsum @78336
// ---------------------------------------------------------------------------
#define SC_K      0
#define SC_KSTAGE 36864
#define SC_Q      73728
#define SC_RMAX   78336
#define SC_RSUM   78848
#define SC_SMEM   79360

__global__ __launch_bounds__(256) void attn_scores_mma(
    const __half* __restrict__ q, const __half* __restrict__ k,
    __half* __restrict__ P)
{
    extern __shared__ char dynsm[];
    uint32_t smbase = (uint32_t)__cvta_generic_to_shared(dynsm);
    float* rmax = (float*)(dynsm + SC_RMAX);
    float* rsum = (float*)(dynsm + SC_RSUM);

    int b = blockIdx.z, h = blockIdx.y, q0 = blockIdx.x * 32;
    int tid = threadIdx.x, lane = tid & 31, wid = tid >> 5;
    int wm = (wid & 1) * 16;
    int wn = (wid >> 1) * 64;

    {
        size_t qb = ((size_t)(b * HH + h) * SS + q0) * HD;
        int row = tid >> 3, c8 = (tid & 7) * 8;
        *(uint4*)(dynsm + SC_Q + (row * 72 + c8) * 2) = *(const uint4*)&q[qb + row * 64 + c8];
    }

    auto load_k = [&](int st, int kt) {
        uint32_t kb = smbase + SC_K + st * SC_KSTAGE;
        size_t gb = ((size_t)(b * HH + h) * SS + kt) * HD;
        #pragma unroll
        for (int it = 0; it < 8; it++) {
            int idx = tid + it * 256;
            int row = idx >> 3, c8 = (idx & 7) * 8;
            cpa16(kb + (uint32_t)(row * 72 + c8) * 2, k + gb + (size_t)row * 64 + c8);
        }
        cp_commit();
    };
    load_k(0, 0);
    load_k(1, 256);

    uint32_t aq_off = (uint32_t)((wm + (lane & 15)) * 72 + (lane >> 4) * 8) * 2;
    int rr_ = lane & 7, halfk = (lane >> 3) & 1, q2 = lane >> 4;

    float acc[4][8][4];
    #pragma unroll
    for (int c = 0; c < 4; c++)
        #pragma unroll
        for (int a = 0; a < 8; a++)
            #pragma unroll
            for (int e = 0; e < 4; e++) acc[c][a][e] = 0.f;

    for (int ch = 0; ch < 4; ch++) {
        if (ch < 3) cp_wait<1>(); else cp_wait<0>();
        __syncthreads();
        uint32_t kb = smbase + SC_K + (ch & 1) * SC_KSTAGE;

        #pragma unroll
        for (int ks = 0; ks < 4; ks++) {
            uint32_t ahf[4];
            ldsm_x4(ahf, smbase + SC_Q + aq_off + ks * 32);
            uint32_t bhf[4][4];
            #pragma unroll
            for (int nb = 0; nb < 4; nb++) {
                uint32_t boff = (uint32_t)((wn + nb * 16 + q2 * 8 + rr_) * 72 + halfk * 8 + ks * 16) * 2;
                ldsm_x4(bhf[nb], kb + boff);
            }
            #pragma unroll
            for (int nb = 0; nb < 4; nb++) {
                mma16816(acc[ch][nb*2],   ahf, bhf[nb]);
                mma16816(acc[ch][nb*2+1], ahf, bhf[nb] + 2);
            }
        }
        __syncthreads();
        if (ch + 2 < 4) load_k((ch + 2) & 1, (ch + 2) * 256);
    }

    // ---- register-resident softmax ----
    int tig = lane & 3, group = lane >> 2;
    int r0 = wm + group, r1 = r0 + 8;
    int wq = wid >> 1;

    float m0 = -1e30f, m1 = -1e30f;
    #pragma unroll
    for (int c = 0; c < 4; c++)
        #pragma unroll
        for (int a = 0; a < 8; a++) {
            m0 = fmaxf(m0, fmaxf(acc[c][a][0], acc[c][a][1]));
            m1 = fmaxf(m1, fmaxf(acc[c][a][2], acc[c][a][3]));
        }
    #pragma unroll
    for (int o = 1; o <= 2; o <<= 1) {
        m0 = fmaxf(m0, __shfl_xor_sync(0xffffffffu, m0, o));
        m1 = fmaxf(m1, __shfl_xor_sync(0xffffffffu, m1, o));
    }
    if (tig == 0) { rmax[r0 * 4 + wq] = m0; rmax[r1 * 4 + wq] = m1; }
    __syncthreads();
    float M0 = fmaxf(fmaxf(rmax[r0*4], rmax[r0*4+1]), fmaxf(rmax[r0*4+2], rmax[r0*4+3]));
    float M1 = fmaxf(fmaxf(rmax[r1*4], rmax[r1*4+1]), fmaxf(rmax[r1*4+2], rmax[r1*4+3]));

    float s0 = 0.f, s1 = 0.f;
    #pragma unroll
    for (int c = 0; c < 4; c++)
        #pragma unroll
        for (int a = 0; a < 8; a++) {
            acc[c][a][0] = __expf((acc[c][a][0] - M0) * QSCALE);
            acc[c][a][1] = __expf((acc[c][a][1] - M0) * QSCALE);
            acc[c][a][2] = __expf((acc[c][a][2] - M1) * QSCALE);
            acc[c][a][3] = __expf((acc[c][a][3] - M1) * QSCALE);
            s0 += acc[c][a][0] + acc[c][a][1];
            s1 += acc[c][a][2] + acc[c][a][3];
        }
    #pragma unroll
    for (int o = 1; o <= 2; o <<= 1) {
        s0 += __shfl_xor_sync(0xffffffffu, s0, o);
        s1 += __shfl_xor_sync(0xffffffffu, s1, o);
    }
    if (tig == 0) { rsum[r0 * 4 + wq] = s0; rsum[r1 * 4 + wq] = s1; }
    __syncthreads();
    float inv0 = 1.f / (rsum[r0*4] + rsum[r0*4+1] + rsum[r0*4+2] + rsum[r0*4+3]);
    float inv1 = 1.f / (rsum[r1*4] + rsum[r1*4+1] + rsum[r1*4+2] + rsum[r1*4+3]);

    size_t gb0 = ((size_t)(b * HH + h) * SS + q0 + r0) * SS;
    size_t gb1 = gb0 + (size_t)8 * SS;
    #pragma unroll
    for (int c = 0; c < 4; c++)
        #pragma unroll
        for (int a = 0; a < 8; a++) {
            int col = c * 256 + wn + a * 8 + tig * 2;
            *(__half2*)&P[gb0 + col] = __halves2half2(
                __float2half_rn(acc[c][a][0] * inv0), __float2half_rn(acc[c][a][1] * inv0));
            *(__half2*)&P[gb1 + col] = __halves2half2(
                __float2half_rn(acc[c][a][2] * inv1), __float2half_rn(acc[c][a][3] * inv1));
        }
}

// ---------------------------------------------------------------------------
// PV: AO = P @ V per (b,h,256q). 1-pass fp16. 2 CTAs/SM.
// ---------------------------------------------------------------------------
#define PV_P  0
#define PV_VH 36864
#define PV_STAGE 46080
#define PV_SMEM 92160

__global__ __launch_bounds__(256, 2) void attn_pv_mma(
    const __half* __restrict__ P, const __half* __restrict__ v,
    __half* __restrict__ AO, int b0)
{
    extern __shared__ char dynsm[];
    uint32_t smbase = (uint32_t)__cvta_generic_to_shared(dynsm);

    int b = blockIdx.z + b0, h = blockIdx.y, q0 = blockIdx.x * 256;
    int tid = threadIdx.x, lane = tid & 31, wid = tid >> 5;

    auto load_stage = [&](int st, int kt) {
        uint32_t sb = smbase + st * PV_STAGE;
        size_t pb = ((size_t)(b * HH + h) * SS + q0) * SS + kt;
        #pragma unroll
        for (int it = 0; it < 8; it++) {
            int idx = tid + it * 256;
            int row = idx >> 3, c8 = (idx & 7) * 8;
            cpa16(sb + PV_P + (uint32_t)(row * 72 + c8) * 2, P + pb + (size_t)row * SS + c8);
        }
        size_t vb = ((size_t)(b * HH + h) * SS + kt) * HD;
        #pragma unroll
        for (int it = 0; it < 2; it++) {
            int idx = tid + it * 256;
            int row = idx >> 3, c8 = (idx & 7) * 8;
            cpa16(sb + PV_VH + (uint32_t)(row * 72 + c8) * 2, v + vb + row * 64 + c8);
        }
        cp_commit();
    };

    float acc[2][8][4];
    #pragma unroll
    for (int a = 0; a < 2; a++)
        #pragma unroll
        for (int j = 0; j < 8; j++)
            #pragma unroll
            for (int c = 0; c < 4; c++) acc[a][j][c] = 0.f;

    uint32_t ap_off = (uint32_t)((wid * 32 + (lane & 15)) * 72 + (lane >> 4) * 8) * 2;
    uint32_t bv_off = (uint32_t)((lane & 15) * 72) * 2;

    load_stage(0, 0);
    load_stage(1, 64);

    for (int i = 0; i < 16; i++) {
        if (i < 15) cp_wait<1>(); else cp_wait<0>();
        __syncthreads();
        uint32_t sb = smbase + (i & 1) * PV_STAGE;
        #pragma unroll
        for (int ks = 0; ks < 4; ks++) {
            uint32_t ahf[2][4];
            #pragma unroll
            for (int mi = 0; mi < 2; mi++) {
                uint32_t off = ap_off + (uint32_t)(mi * 16 * 72 + ks * 16) * 2;
                ldsm_x4(ahf[mi], sb + PV_P + off);
            }
            #pragma unroll
            for (int nb = 0; nb < 2; nb++) {
                uint32_t bhf[4][2];
                #pragma unroll
                for (int nj = 0; nj < 4; nj++) {
                    uint32_t off = bv_off + (uint32_t)(ks * 16 * 72 + (nb * 4 + nj) * 8) * 2;
                    ldsm_x2t(bhf[nj], sb + PV_VH + off);
                }
                #pragma unroll
                for (int nj = 0; nj < 4; nj++)
                    #pragma unroll
                    for (int mi = 0; mi < 2; mi++)
                        mma16816(acc[mi][nb*4+nj], ahf[mi], bhf[nj]);
            }
        }
        __syncthreads();
        if (i + 2 < 16) load_stage((i + 2) & 1, (i + 2) * 64);
    }

    int group = lane >> 2, tig = lane & 3;
    #pragma unroll
    for (int mi = 0; mi < 2; mi++) {
        #pragma unroll
        for (int ni = 0; ni < 8; ni++) {
            int d = ni * 8 + tig * 2;
            int r0 = q0 + wid * 32 + mi * 16 + group;
            size_t o0 = (size_t)(b * SS + r0) * DD + h * HD + d;
            size_t o1 = o0 + (size_t)8 * DD;
            *(__half2*)&AO[o0] = __halves2half2(
                __float2half_rn(acc[mi][ni][0]), __float2half_rn(acc[mi][ni][1]));
            *(__half2*)&AO[o1] = __halves2half2(
                __float2half_rn(acc[mi][ni][2]), __float2half_rn(acc[mi][ni][3]));
        }
    }
}

// ---------------------------------------------------------------------------
// attn_mean[b,q,k] = (1/H) * sum_h P
// ---------------------------------------------------------------------------
__global__ __launch_bounds__(256) void attn_mean_kernel(
    const __half* __restrict__ P, float* __restrict__ outm)
{
    size_t g = (size_t)blockIdx.x * 256 + threadIdx.x;
    int k8 = (int)(g & 127);
    size_t t = g >> 7;
    int q = (int)(t & 1023);
    int b = (int)(t >> 10);
    size_t k = (size_t)k8 * 8;

    float acc8[8];
    #pragma unroll
    for (int j = 0; j < 8; j++) acc8[j] = 0.f;
    #pragma unroll
    for (int h = 0; h < HH; h++) {
        size_t off = ((size_t)(b * HH + h) * SS + q) * SS + k;
        uint4 v4 = *(const uint4*)&P[off];
        const uint32_t* p = (const uint32_t*)&v4;
        #pragma unroll
        for (int j = 0; j < 4; j++) {
            float2 hh = __half22float2(*(__half2*)&p[j]);
            acc8[2*j]   += hh.x;
            acc8[2*j+1] += hh.y;
        }
    }
    size_t ob = ((size_t)(b * SS + q)) * SS + k;
    const float inv = 1.0f / HH;
    float4 o0 = make_float4(acc8[0]*inv, acc8[1]*inv, acc8[2]*inv, acc8[3]*inv);
    float4 o1 = make_float4(acc8[4]*inv, acc8[5]*inv, acc8[6]*inv, acc8[7]*inv);
    *(float4*)&outm[ob]     = o0;
    *(float4*)&outm[ob + 4] = o1;
}

// ---------------------------------------------------------------------------
// Host launcher: legal event-forked dual-stream schedule (proven R16 shape).
// ---------------------------------------------------------------------------
extern "C" void kernel_launch(void* const* d_in, const int* in_sizes, int n_in,
                              void* d_out, int out_size)
{
    const float* x     = (const float*)d_in[0];
    const float* w_in  = (const float*)d_in[1];
    const float* b_in  = (const float*)d_in[2];
    const float* w_out = (const float*)d_in[3];
    const float* b_out = (const float*)d_in[4];
    float* out = (float*)d_out;

    __half *xh, *wih, *woh;
    __half *q, *k, *v, *p, *ao;
    cudaGetSymbolAddress((void**)&xh,  g_xh);
    cudaGetSymbolAddress((void**)&wih, g_wih);
    cudaGetSymbolAddress((void**)&woh, g_woh);
    cudaGetSymbolAddress((void**)&q,   g_q);
    cudaGetSymbolAddress((void**)&k,   g_k);
    cudaGetSymbolAddress((void**)&v,   g_v);
    cudaGetSymbolAddress((void**)&p,   g_p);
    cudaGetSymbolAddress((void**)&ao,  g_ao);

    static cudaStream_t s1 = nullptr;
    static cudaEvent_t ev0 = nullptr, evX = nullptr, evV = nullptr,
                       evA = nullptr, evP0 = nullptr, evB = nullptr;
    if (!s1) {
        cudaStreamCreateWithFlags(&s1, cudaStreamNonBlocking);
        cudaEventCreateWithFlags(&ev0, cudaEventDisableTiming);
        cudaEventCreateWithFlags(&evX, cudaEventDisableTiming);
        cudaEventCreateWithFlags(&evV, cudaEventDisableTiming);
        cudaEventCreateWithFlags(&evA, cudaEventDisableTiming);
        cudaEventCreateWithFlags(&evP0, cudaEventDisableTiming);
        cudaEventCreateWithFlags(&evB, cudaEventDisableTiming);
    }

    cudaFuncSetAttribute(mma_gemm_qkv,
                         cudaFuncAttributeMaxDynamicSharedMemorySize, GEMM_SMEM);
    cudaFuncSetAttribute(mma_gemm_out,
                         cudaFuncAttributeMaxDynamicSharedMemorySize, GEMM_SMEM);
    cudaFuncSetAttribute(attn_scores_mma,
                         cudaFuncAttributeMaxDynamicSharedMemorySize, SC_SMEM);
    cudaFuncSetAttribute(attn_pv_mma,
                         cudaFuncAttributeMaxDynamicSharedMemorySize, PV_SMEM);

    // fork s1 legally off the capture-origin stream
    cudaEventRecord(ev0, 0);
    cudaStreamWaitEvent(s1, ev0, 0);

    // main: converts for x and w_in
    cvt_kernel<<<(MROWS * DD / 4 + 255) / 256, 256>>>(x, xh, MROWS * DD / 4);
    cvt_kernel<<<(DD * 3 * DD / 4 + 255) / 256, 256>>>(w_in, wih, DD * 3 * DD / 4);
    cudaEventRecord(evX, 0);

    // s1: w_out convert, then v-part of QKV (overlaps qk-GEMM + scores)
    cvt_kernel<<<(DD * DD / 4 + 255) / 256, 256, 0, s1>>>(w_out, woh, DD * DD / 4);
    cudaStreamWaitEvent(s1, evX, 0);
    mma_gemm_qkv<<<dim3(8, MROWS / 128), 256, GEMM_SMEM, s1>>>(
        xh, wih, b_in, q, k, v, MROWS, 3 * DD, DD, 16);   // v third
    cudaEventRecord(evV, s1);

    // main: qk two-thirds of QKV
    mma_gemm_qkv<<<dim3(16, MROWS / 128), 256, GEMM_SMEM>>>(
        xh, wih, b_in, q, k, v, MROWS, 3 * DD, DD, 0);

    // main: scores (register-resident softmax)
    attn_scores_mma<<<dim3(SS / 32, HH, BB), 256, SC_SMEM>>>(q, k, p);
    cudaEventRecord(evA, 0);

    // main: PV half 0 (needs v)
    cudaStreamWaitEvent(0, evV, 0);
    attn_pv_mma<<<dim3(SS / 256, HH, 2), 256, PV_SMEM>>>(p, v, ao, 0);
    cudaEventRecord(evP0, 0);

    // main: PV half 1
    attn_pv_mma<<<dim3(SS / 256, HH, 2), 256, PV_SMEM>>>(p, v, ao, 2);

    // s1: out-proj rows 0..2047 (overlaps PV half 1), then mean
    cudaStreamWaitEvent(s1, evP0, 0);
    mma_gemm_out<<<dim3(8, 16), 256, GEMM_SMEM, s1>>>(
        ao, woh, b_out, out, MROWS, DD, DD, 0);
    cudaStreamWaitEvent(s1, evA, 0);
    attn_mean_kernel<<<(BB * SS * SS / 8) / 256, 256, 0, s1>>>(
        p, out + (size_t)BB * SS * SS);
    cudaEventRecord(evB, s1);

    // main: out-proj rows 2048..4095
    mma_gemm_out<<<dim3(8, 16), 256, GEMM_SMEM>>>(
        ao, woh, b_out, out, MROWS, DD, DD, 16);

    // join
    cudaStreamWaitEvent(0, evB, 0);
}